// round 10
// baseline (speedup 1.0000x reference)
#include <cuda_runtime.h>
#include <cuda_bf16.h>
#include <math.h>
#include <stdint.h>

// ---------------- problem constants ----------------
#define BQ   4
#define SQ   512
#define DQ   768
#define HQ   12
#define HDQ  64
#define LQ   12
#define VQ   50257
#define VQP  50304
#define FFQ  3072
#define NT   (BQ*SQ)

#define WQ_OFF  0
#define WK_OFF  589824
#define WV_OFF  1179648
#define WO_OFF  1769472
#define W1T_OFF 2359296
#define W2T_OFF 4718592
#define LSZ     7077888
#define WOUT_OFF (12*LSZ)
#define WTOT     (WOUT_OFF + (long)VQP*DQ)

// ---------------- static scratch ----------------
__device__ __align__(128) float    g_h   [NT*DQ];
__device__ __align__(128) float    g_q   [NT*DQ];
__device__ __align__(128) float    g_k   [NT*DQ];
__device__ __align__(128) float    g_v   [NT*DQ];
__device__ __align__(128) uint16_t g_hnh [NT*DQ],  g_hnl [NT*DQ];
__device__ __align__(128) uint16_t g_ctxh[NT*DQ],  g_ctxl[NT*DQ];
__device__ __align__(128) uint16_t g_ffh [NT*FFQ], g_ffl [NT*FFQ];
__device__ __align__(128) uint16_t g_wth [WTOT];
__device__ __align__(128) uint16_t g_wtl [WTOT];

// ---------------- helpers ----------------
__device__ __forceinline__ float gelu_f(float x) {
    const float c = 0.7978845608028654f;
    float x3 = x * x * x;
    return 0.5f * x * (1.0f + tanhf(c * (x + 0.044715f * x3)));
}

__device__ __forceinline__ uint32_t smem_u32(const void* p) {
    uint32_t a;
    asm("{ .reg .u64 t; cvta.to.shared.u64 t, %1; cvt.u32.u64 %0, t; }" : "=r"(a) : "l"(p));
    return a;
}

__device__ __forceinline__ void split2(float a, float b, uint32_t& hi, uint32_t& lo) {
    __nv_bfloat16 ha = __float2bfloat16_rn(a), hb = __float2bfloat16_rn(b);
    float ra = a - __bfloat162float(ha), rb = b - __bfloat162float(hb);
    __nv_bfloat16 la = __float2bfloat16_rn(ra), lb = __float2bfloat16_rn(rb);
    hi = ((uint32_t)__bfloat16_as_ushort(hb) << 16) | (uint32_t)__bfloat16_as_ushort(ha);
    lo = ((uint32_t)__bfloat16_as_ushort(lb) << 16) | (uint32_t)__bfloat16_as_ushort(la);
}

__device__ __forceinline__ void ldsm4(uint32_t& r0, uint32_t& r1, uint32_t& r2, uint32_t& r3,
                                      uint32_t addr) {
    asm volatile("ldmatrix.sync.aligned.m8n8.x4.shared.b16 {%0,%1,%2,%3}, [%4];"
        : "=r"(r0), "=r"(r1), "=r"(r2), "=r"(r3) : "r"(addr));
}

__device__ __forceinline__ void mma_bf16(float* c, const uint32_t* a, const uint32_t* b) {
    asm volatile("mma.sync.aligned.m16n8k16.row.col.f32.bf16.bf16.f32 "
        "{%0,%1,%2,%3}, {%4,%5,%6,%7}, {%8,%9}, {%0,%1,%2,%3};"
        : "+f"(c[0]), "+f"(c[1]), "+f"(c[2]), "+f"(c[3])
        : "r"(a[0]), "r"(a[1]), "r"(a[2]), "r"(a[3]), "r"(b[0]), "r"(b[1]));
}

__device__ __forceinline__ void cpa16(uint32_t saddr, const void* g) {
    asm volatile("cp.async.cg.shared.global [%0], [%1], 16;" :: "r"(saddr), "l"(g));
}

// ---------------- weight transpose+split, batched over layers (grid.z) ----------------
__global__ void gpt_wsplit(const float* __restrict__ W, uint16_t* __restrict__ Th,
                           uint16_t* __restrict__ Tl, int K, int N, int Npad,
                           long ws, long ts) {
    int l = blockIdx.z;
    W  += (long)l * ws;
    Th += (long)l * ts;
    Tl += (long)l * ts;
    __shared__ float t[32][33];
    int n0 = blockIdx.x * 32, k0 = blockIdx.y * 32;
    int tx = threadIdx.x, ty = threadIdx.y;
    #pragma unroll
    for (int j = 0; j < 4; j++) {
        int n = n0 + tx;
        t[ty + j * 8][tx] = (n < N) ? W[(long)(k0 + ty + j * 8) * N + n] : 0.f;
    }
    __syncthreads();
    #pragma unroll
    for (int j = 0; j < 4; j++) {
        int n = n0 + ty + j * 8;
        if (n < Npad) {
            float v = t[tx][ty + j * 8];
            __nv_bfloat16 hb = __float2bfloat16_rn(v);
            float r = v - __bfloat162float(hb);
            Th[(long)n * K + k0 + tx] = __bfloat16_as_ushort(hb);
            Tl[(long)n * K + k0 + tx] = __bfloat16_as_ushort(__float2bfloat16_rn(r));
        }
    }
}

// ---------------- embedding ----------------
__global__ void gpt_embed(const int* __restrict__ x, const float* __restrict__ tok,
                          const float* __restrict__ pos, float* __restrict__ h) {
    int i = blockIdx.x * blockDim.x + threadIdx.x;
    if (i < NT * DQ) {
        int t = i / DQ, d = i - t * DQ;
        int s = t & (SQ - 1);
        h[i] = tok[(long)x[t] * DQ + d] + pos[s * DQ + d];
    }
}

// ---------------- layernorm -> bf16 hi/lo ----------------
__global__ void gpt_ln(const float* __restrict__ in, const float* __restrict__ scale,
                       const float* __restrict__ shift,
                       uint16_t* __restrict__ oh, uint16_t* __restrict__ ol) {
    int t = blockIdx.x;
    const float* row = in + (long)t * DQ;
    __shared__ float red[256];
    int tid = threadIdx.x;

    float s = 0.f;
    for (int d = tid; d < DQ; d += 256) s += row[d];
    red[tid] = s; __syncthreads();
    for (int o = 128; o > 0; o >>= 1) { if (tid < o) red[tid] += red[tid + o]; __syncthreads(); }
    float mean = red[0] * (1.0f / DQ); __syncthreads();

    float sq = 0.f;
    for (int d = tid; d < DQ; d += 256) { float v = row[d] - mean; sq += v * v; }
    red[tid] = sq; __syncthreads();
    for (int o = 128; o > 0; o >>= 1) { if (tid < o) red[tid] += red[tid + o]; __syncthreads(); }
    float inv = rsqrtf(red[0] * (1.0f / DQ) + 1e-5f);

    long base = (long)t * DQ;
    for (int d = tid; d < DQ; d += 256) {
        float v = scale[d] * (row[d] - mean) * inv + shift[d];
        __nv_bfloat16 hb = __float2bfloat16_rn(v);
        float r = v - __bfloat162float(hb);
        oh[base + d] = __bfloat16_as_ushort(hb);
        ol[base + d] = __bfloat16_as_ushort(__float2bfloat16_rn(r));
    }
}

// ---------------- bf16x3 GEMM, BM=64, 2 CTAs/SM, 2-stage cp.async ----------------
// stage: Ah(64 rows) | Al | Bh(128 rows) | Bl, rows of 80B (32 K-halves + pad).
#define BM   64
#define OAL  (BM * 80)          // 5120
#define OBH  (2 * BM * 80)      // 10240
#define OBL  (OBH + 10240)      // 20480
#define STG  ((2 * BM + 256) * 80)  // 30720

__device__ __forceinline__ void load_stage(uint32_t sst,
    const uint16_t* __restrict__ Ah, const uint16_t* __restrict__ Al,
    const uint16_t* __restrict__ Bh, const uint16_t* __restrict__ Bl,
    int bm, int bn, int K, int c, int tid) {
    #pragma unroll
    for (int p = 0; p < 2; p++) {
        int idx = tid + p * 256;
        int row = idx >> 2, seg = idx & 3;
        long go = (long)row * K + c * 32 + seg * 8;
        uint32_t so = row * 80 + seg * 16;
        cpa16(sst + OBH + so, Bh + (long)bn * K + go);
        cpa16(sst + OBL + so, Bl + (long)bn * K + go);
        if (row < BM) {
            cpa16(sst + so,       Ah + (long)bm * K + go);
            cpa16(sst + OAL + so, Al + (long)bm * K + go);
        }
    }
    asm volatile("cp.async.commit_group;" ::: "memory");
}

__device__ __forceinline__ void mma_stage(uint32_t sst, float acc[2][4][4],
        int wm, int wn, int a_row, int a_kof, int b_nof, int b_kof) {
    #pragma unroll
    for (int kk = 0; kk < 32; kk += 16) {
        uint32_t fah[2][4], fal[2][4], fbh[4][2], fbl[4][2];
        #pragma unroll
        for (int ma = 0; ma < 2; ma++) {
            uint32_t ro = (uint32_t)((wm * 32 + ma * 16 + a_row) * 80 + (kk + a_kof) * 2);
            ldsm4(fah[ma][0], fah[ma][1], fah[ma][2], fah[ma][3], sst + ro);
        }
        #pragma unroll
        for (int np = 0; np < 2; np++) {
            uint32_t ro = (uint32_t)((wn * 32 + np * 16 + b_nof) * 80 + (kk + b_kof) * 2);
            ldsm4(fbh[2*np][0], fbh[2*np][1], fbh[2*np+1][0], fbh[2*np+1][1], sst + OBH + ro);
        }
        #pragma unroll
        for (int ma = 0; ma < 2; ma++)
            #pragma unroll
            for (int na = 0; na < 4; na++)
                mma_bf16(acc[ma][na], fah[ma], fbh[na]);
        #pragma unroll
        for (int np = 0; np < 2; np++) {
            uint32_t ro = (uint32_t)((wn * 32 + np * 16 + b_nof) * 80 + (kk + b_kof) * 2);
            ldsm4(fbl[2*np][0], fbl[2*np][1], fbl[2*np+1][0], fbl[2*np+1][1], sst + OBL + ro);
        }
        #pragma unroll
        for (int ma = 0; ma < 2; ma++)
            #pragma unroll
            for (int na = 0; na < 4; na++)
                mma_bf16(acc[ma][na], fah[ma], fbl[na]);
        #pragma unroll
        for (int ma = 0; ma < 2; ma++) {
            uint32_t ro = (uint32_t)((wm * 32 + ma * 16 + a_row) * 80 + (kk + a_kof) * 2);
            ldsm4(fal[ma][0], fal[ma][1], fal[ma][2], fal[ma][3], sst + ro + OAL);
        }
        #pragma unroll
        for (int ma = 0; ma < 2; ma++)
            #pragma unroll
            for (int na = 0; na < 4; na++)
                mma_bf16(acc[ma][na], fal[ma], fbh[na]);
    }
}

// EPI: 0 fp32 plain; 2 fp32 +bias+res; 3 gelu(x+bias)->bf16 hi/lo. NG: guard gn.
template<int EPI, bool NG>
__device__ __forceinline__ void bmma_core(
    const uint16_t* __restrict__ Ah, const uint16_t* __restrict__ Al,
    const uint16_t* __restrict__ Bh, const uint16_t* __restrict__ Bl,
    const float* __restrict__ bias, const float* __restrict__ res,
    float* __restrict__ C, uint16_t* __restrict__ Ch, uint16_t* __restrict__ Cl,
    int Ntot, int K, int ldc, int miter) {
    extern __shared__ __align__(16) char smem[];
    uint32_t sb = smem_u32(smem);
    int tid = threadIdx.x;
    int lane = tid & 31, wid = tid >> 5;
    int wm = wid >> 2, wn = wid & 3;
    int bn = blockIdx.x * 128;

    int l8 = lane & 7;
    int a_row = ((lane >> 3) & 1) * 8 + l8;
    int a_kof = (lane >> 4) * 8;
    int b_nof = (lane >> 4) * 8 + l8;
    int b_kof = ((lane >> 3) & 1) * 8;
    int g = lane >> 2, tig = lane & 3;
    const int NCH = K >> 5;

    for (int mi = 0; mi < miter; mi++) {
        int bm = (blockIdx.y * miter + mi) * BM;
        if (mi) __syncthreads();

        float acc[2][4][4];
        #pragma unroll
        for (int i = 0; i < 2; i++)
            #pragma unroll
            for (int j = 0; j < 4; j++)
                #pragma unroll
                for (int r2 = 0; r2 < 4; r2++) acc[i][j][r2] = 0.f;

        load_stage(sb, Ah, Al, Bh, Bl, bm, bn, K, 0, tid);

        for (int c = 0; c < NCH; c++) {
            if (c + 1 < NCH) {
                load_stage(sb + ((c + 1) & 1) * STG, Ah, Al, Bh, Bl, bm, bn, K, c + 1, tid);
                asm volatile("cp.async.wait_group 1;" ::: "memory");
            } else {
                asm volatile("cp.async.wait_group 0;" ::: "memory");
            }
            __syncthreads();
            mma_stage(sb + (c & 1) * STG, acc, wm, wn, a_row, a_kof, b_nof, b_kof);
            if (c + 1 < NCH) __syncthreads();
        }

        #pragma unroll
        for (int ma = 0; ma < 2; ma++) {
            int r0 = bm + wm * 32 + ma * 16 + g;
            #pragma unroll
            for (int na = 0; na < 4; na++) {
                int gn = bn + wn * 32 + na * 8 + 2 * tig;
                #pragma unroll
                for (int half = 0; half < 2; half++) {
                    int gm = r0 + half * 8;
                    float v0 = acc[ma][na][half * 2 + 0];
                    float v1 = acc[ma][na][half * 2 + 1];
                    long gi = (long)gm * ldc + gn;
                    if (NG) {
                        if (gn < Ntot)     C[gi]     = v0;
                        if (gn + 1 < Ntot) C[gi + 1] = v1;
                    } else if (EPI == 3) {
                        v0 = gelu_f(v0 + bias[gn]);
                        v1 = gelu_f(v1 + bias[gn + 1]);
                        uint32_t hh, ll;
                        split2(v0, v1, hh, ll);
                        *(uint32_t*)&Ch[gi] = hh;
                        *(uint32_t*)&Cl[gi] = ll;
                    } else {
                        if (EPI == 2) {
                            v0 += bias[gn]     + res[gi];
                            v1 += bias[gn + 1] + res[gi + 1];
                        }
                        *(float2*)&C[gi] = make_float2(v0, v1);
                    }
                }
            }
        }
    }
}

template<int EPI, bool NG>
__global__ void __launch_bounds__(256, 2)
gpt_bmma(const uint16_t* __restrict__ Ah, const uint16_t* __restrict__ Al,
         const uint16_t* __restrict__ Bh, const uint16_t* __restrict__ Bl,
         const float* __restrict__ bias, const float* __restrict__ res,
         float* __restrict__ C, uint16_t* __restrict__ Ch, uint16_t* __restrict__ Cl,
         int Ntot, int K, int ldc, int miter) {
    bmma_core<EPI, NG>(Ah, Al, Bh, Bl, bias, res, C, Ch, Cl, Ntot, K, ldc, miter);
}

__global__ void __launch_bounds__(256, 2)
gpt_bmma_qkv(const uint16_t* __restrict__ Ah, const uint16_t* __restrict__ Al,
             const uint16_t* __restrict__ Wth, const uint16_t* __restrict__ Wtl,
             float* __restrict__ Oq, float* __restrict__ Ok, float* __restrict__ Ov) {
    int z = blockIdx.z;
    const uint16_t* Bh = Wth + (long)z * 589824;
    const uint16_t* Bl = Wtl + (long)z * 589824;
    float* C = (z == 0) ? Oq : (z == 1) ? Ok : Ov;
    bmma_core<0, false>(Ah, Al, Bh, Bl, nullptr, nullptr, C, nullptr, nullptr,
                        DQ, DQ, DQ, 1);
}

// ---------------- fused flash attention (epilogue -> bf16 hi/lo ctx) ----------------
__global__ void __launch_bounds__(256, 2)
gpt_flash(const float* __restrict__ Q, const float* __restrict__ Kx,
          const float* __restrict__ Vx,
          uint16_t* __restrict__ ctxh, uint16_t* __restrict__ ctxl) {
    extern __shared__ float sm[];
    float* Qs   = sm;
    float* Ks   = sm + 4096;
    float* Vs   = sm + 8192;
    float* rowm = sm + 12288;
    float* rowl = rowm + 64;
    float* rowf = rowm + 128;

    int z = blockIdx.y;
    int b = z / HQ, h = z - b * HQ;
    int qt = blockIdx.x, q0 = qt * 64;
    int tid = threadIdx.x;
    int r = tid & 63, dg = tid >> 6;
    int ty = tid >> 4, tx = tid & 15;

    {
        const float* qrow = Q + ((long)(b * SQ + q0 + r)) * DQ + h * HDQ + dg * 16;
        #pragma unroll
        for (int i = 0; i < 4; i++) {
            float4 t = *(const float4*)(qrow + i * 4);
            int d = dg * 16 + i * 4;
            Qs[(d + 0) * 64 + r] = t.x; Qs[(d + 1) * 64 + r] = t.y;
            Qs[(d + 2) * 64 + r] = t.z; Qs[(d + 3) * 64 + r] = t.w;
        }
    }
    if (tid < 64) { rowm[tid] = -1e30f; rowl[tid] = 0.f; }

    float o[4][4] = {};

    for (int j = 0; j <= qt; j++) {
        int k0 = j * 64;
        __syncthreads();
        {
            const float* krow = Kx + ((long)(b * SQ + k0 + r)) * DQ + h * HDQ + dg * 16;
            const float* vrow = Vx + ((long)(b * SQ + k0 + r)) * DQ + h * HDQ + dg * 16;
            #pragma unroll
            for (int i = 0; i < 4; i++) {
                float4 t = *(const float4*)(krow + i * 4);
                int d = dg * 16 + i * 4;
                Ks[(d + 0) * 64 + r] = t.x; Ks[(d + 1) * 64 + r] = t.y;
                Ks[(d + 2) * 64 + r] = t.z; Ks[(d + 3) * 64 + r] = t.w;
                float4 tv = *(const float4*)(vrow + i * 4);
                *(float4*)&Vs[r * 64 + dg * 16 + i * 4] = tv;
            }
        }
        __syncthreads();

        float s[4][4] = {};
        #pragma unroll 8
        for (int d = 0; d < 64; d++) {
            float qv[4], kv[4];
            #pragma unroll
            for (int i = 0; i < 4; i++) qv[i] = Qs[d * 64 + ty * 4 + i];
            #pragma unroll
            for (int c = 0; c < 4; c++) kv[c] = Ks[d * 64 + tx * 4 + c];
            #pragma unroll
            for (int i = 0; i < 4; i++)
                #pragma unroll
                for (int c = 0; c < 4; c++)
                    s[i][c] += qv[i] * kv[c];
        }
        #pragma unroll
        for (int i = 0; i < 4; i++)
            #pragma unroll
            for (int c = 0; c < 4; c++) {
                s[i][c] *= 0.125f;
                if (j == qt && (k0 + tx * 4 + c) > (q0 + ty * 4 + i)) s[i][c] = -1e30f;
            }
        __syncthreads();
        #pragma unroll
        for (int i = 0; i < 4; i++)
            #pragma unroll
            for (int c = 0; c < 4; c++)
                Ks[(ty * 4 + i) * 64 + tx * 4 + c] = s[i][c];
        __syncthreads();

        if (tid < 64) {
            float m_old = rowm[tid], m = m_old;
            #pragma unroll 8
            for (int t = 0; t < 64; t++) {
                int kk = (t + tid) & 63;
                m = fmaxf(m, Ks[tid * 64 + kk]);
            }
            float f = __expf(m_old - m);
            float l = rowl[tid] * f;
            #pragma unroll 8
            for (int t = 0; t < 64; t++) {
                int kk = (t + tid) & 63;
                float p = __expf(Ks[tid * 64 + kk] - m);
                Ks[tid * 64 + kk] = p;
                l += p;
            }
            rowm[tid] = m; rowl[tid] = l; rowf[tid] = f;
        }
        __syncthreads();

        float fr[4];
        #pragma unroll
        for (int i = 0; i < 4; i++) fr[i] = rowf[ty * 4 + i];
        #pragma unroll
        for (int i = 0; i < 4; i++)
            #pragma unroll
            for (int c = 0; c < 4; c++) o[i][c] *= fr[i];
        #pragma unroll 8
        for (int kk = 0; kk < 64; kk++) {
            float p[4];
            #pragma unroll
            for (int i = 0; i < 4; i++) p[i] = Ks[(ty * 4 + i) * 64 + kk];
            float4 vv = *(const float4*)&Vs[kk * 64 + tx * 4];
            #pragma unroll
            for (int i = 0; i < 4; i++) {
                o[i][0] += p[i] * vv.x; o[i][1] += p[i] * vv.y;
                o[i][2] += p[i] * vv.z; o[i][3] += p[i] * vv.w;
            }
        }
    }

    #pragma unroll
    for (int i = 0; i < 4; i++) {
        float inv = 1.0f / rowl[ty * 4 + i];
        float v0 = o[i][0] * inv, v1 = o[i][1] * inv;
        float v2 = o[i][2] * inv, v3 = o[i][3] * inv;
        uint32_t h01, l01, h23, l23;
        split2(v0, v1, h01, l01);
        split2(v2, v3, h23, l23);
        long base = ((long)(b * SQ + q0 + ty * 4 + i)) * DQ + h * HDQ + tx * 4;
        *(uint2*)&ctxh[base] = make_uint2(h01, h23);
        *(uint2*)&ctxl[base] = make_uint2(l01, l23);
    }
}

// ---------------- host orchestration ----------------
extern "C" void kernel_launch(void* const* d_in, const int* in_sizes, int n_in,
                              void* d_out, int out_size) {
    const int*   x    = (const int*)  d_in[0];
    const float* tok  = (const float*)d_in[1];
    const float* pos  = (const float*)d_in[2];
    const float* ln1s = (const float*)d_in[3];
    const float* ln1b = (const float*)d_in[4];
    const float* wq   = (const float*)d_in[5];
    const float* wk   = (const float*)d_in[6];
    const float* wv   = (const float*)d_in[7];
    const float* wo   = (const float*)d_in[8];
    const float* bo   = (const float*)d_in[9];
    const float* ln2s = (const float*)d_in[10];
    const float* ln2b = (const float*)d_in[11];
    const float* w1   = (const float*)d_in[12];
    const float* b1   = (const float*)d_in[13];
    const float* w2   = (const float*)d_in[14];
    const float* b2   = (const float*)d_in[15];
    const float* fs   = (const float*)d_in[16];
    const float* fb   = (const float*)d_in[17];
    const float* wout = (const float*)d_in[18];
    float* out = (float*)d_out;

    float *h, *q, *k, *v;
    uint16_t *hnh, *hnl, *ctxh, *ctxl, *ffh, *ffl, *wth, *wtl;
    cudaGetSymbolAddress((void**)&h,    g_h);
    cudaGetSymbolAddress((void**)&q,    g_q);
    cudaGetSymbolAddress((void**)&k,    g_k);
    cudaGetSymbolAddress((void**)&v,    g_v);
    cudaGetSymbolAddress((void**)&hnh,  g_hnh);
    cudaGetSymbolAddress((void**)&hnl,  g_hnl);
    cudaGetSymbolAddress((void**)&ctxh, g_ctxh);
    cudaGetSymbolAddress((void**)&ctxl, g_ctxl);
    cudaGetSymbolAddress((void**)&ffh,  g_ffh);
    cudaGetSymbolAddress((void**)&ffl,  g_ffl);
    cudaGetSymbolAddress((void**)&wth,  g_wth);
    cudaGetSymbolAddress((void**)&wtl,  g_wtl);

    const int FLASH_SMEM = (64 * 64 * 3 + 64 * 3) * sizeof(float); // 49920
    const int GSMEM = 2 * STG;                                      // 61440
    cudaFuncSetAttribute(gpt_flash, cudaFuncAttributeMaxDynamicSharedMemorySize, FLASH_SMEM);
    cudaFuncSetAttribute((const void*)gpt_bmma<2, false>, cudaFuncAttributeMaxDynamicSharedMemorySize, GSMEM);
    cudaFuncSetAttribute((const void*)gpt_bmma<3, false>, cudaFuncAttributeMaxDynamicSharedMemorySize, GSMEM);
    cudaFuncSetAttribute((const void*)gpt_bmma<0, true>,  cudaFuncAttributeMaxDynamicSharedMemorySize, GSMEM);
    cudaFuncSetAttribute((const void*)gpt_bmma_qkv,       cudaFuncAttributeMaxDynamicSharedMemorySize, GSMEM);

    // ---- weight transpose+split, batched over layers ----
    dim3 wt(32, 8);
    gpt_wsplit<<<dim3(24, 24, 12), wt>>>(wq,  wth + WQ_OFF,  wtl + WQ_OFF,  DQ, DQ, DQ,
                                         (long)DQ*DQ,  (long)LSZ);
    gpt_wsplit<<<dim3(24, 24, 12), wt>>>(wk,  wth + WK_OFF,  wtl + WK_OFF,  DQ, DQ, DQ,
                                         (long)DQ*DQ,  (long)LSZ);
    gpt_wsplit<<<dim3(24, 24, 12), wt>>>(wv,  wth + WV_OFF,  wtl + WV_OFF,  DQ, DQ, DQ,
                                         (long)DQ*DQ,  (long)LSZ);
    gpt_wsplit<<<dim3(24, 24, 12), wt>>>(wo,  wth + WO_OFF,  wtl + WO_OFF,  DQ, DQ, DQ,
                                         (long)DQ*DQ,  (long)LSZ);
    gpt_wsplit<<<dim3(96, 24, 12), wt>>>(w1,  wth + W1T_OFF, wtl + W1T_OFF, DQ, FFQ, FFQ,
                                         (long)DQ*FFQ, (long)LSZ);
    gpt_wsplit<<<dim3(24, 96, 12), wt>>>(w2,  wth + W2T_OFF, wtl + W2T_OFF, FFQ, DQ, DQ,
                                         (long)FFQ*DQ, (long)LSZ);
    gpt_wsplit<<<dim3(VQP / 32, 24, 1), wt>>>(wout, wth + WOUT_OFF, wtl + WOUT_OFF,
                                         DQ, VQ, VQP, 0, 0);

    gpt_embed<<<(NT * DQ + 255) / 256, 256>>>(x, tok, pos, h);

    dim3 gP (DQ / 128,  NT / 64);         // (6,32)
    dim3 gQ (DQ / 128,  NT / 64, 3);      // (6,32,3)
    dim3 gF1(FFQ / 128, NT / 64);         // (24,32)
    dim3 gV (VQP / 128, 8);               // (393,8) miter=4 -> 8*4*64 = 2048 rows
    dim3 gFl(SQ / 64,   BQ * HQ);         // (8,48)

    for (int l = 0; l < LQ; l++) {
        long lo = (long)l * LSZ;

        gpt_ln<<<NT, 256>>>(h, ln1s + l * DQ, ln1b + l * DQ, hnh, hnl);

        gpt_bmma_qkv<<<gQ, 256, GSMEM>>>(hnh, hnl, wth + lo + WQ_OFF, wtl + lo + WQ_OFF,
                                         q, k, v);

        gpt_flash<<<gFl, 256, FLASH_SMEM>>>(q, k, v, ctxh, ctxl);

        gpt_bmma<2, false><<<gP, 256, GSMEM>>>(ctxh, ctxl,
            wth + lo + WO_OFF, wtl + lo + WO_OFF, bo + l * DQ, h, h, nullptr, nullptr,
            DQ, DQ, DQ, 1);

        gpt_ln<<<NT, 256>>>(h, ln2s + l * DQ, ln2b + l * DQ, hnh, hnl);

        gpt_bmma<3, false><<<gF1, 256, GSMEM>>>(hnh, hnl,
            wth + lo + W1T_OFF, wtl + lo + W1T_OFF, b1 + l * FFQ, nullptr,
            nullptr, ffh, ffl, FFQ, DQ, FFQ, 1);

        gpt_bmma<2, false><<<gP, 256, GSMEM>>>(ffh, ffl,
            wth + lo + W2T_OFF, wtl + lo + W2T_OFF, b2 + l * DQ, h, h, nullptr, nullptr,
            DQ, FFQ, DQ, 1);
    }

    gpt_ln<<<NT, 256>>>(h, fs, fb, hnh, hnl);

    gpt_bmma<0, true><<<gV, 256, GSMEM>>>(hnh, hnl,
        wth + WOUT_OFF, wtl + WOUT_OFF, nullptr, nullptr, out, nullptr, nullptr,
        VQ, DQ, VQ, 4);
}

// round 11
// speedup vs baseline: 1.2287x; 1.2287x over previous
#include <cuda_runtime.h>
#include <cuda_fp16.h>
#include <math.h>
#include <stdint.h>

// ---------------- problem constants ----------------
#define BQ   4
#define SQ   512
#define DQ   768
#define HQ   12
#define HDQ  64
#define LQ   12
#define VQ   50257
#define VQP  50304
#define FFQ  3072
#define NT   (BQ*SQ)

#define WQ_OFF  0
#define WK_OFF  589824
#define WV_OFF  1179648
#define WO_OFF  1769472
#define W1T_OFF 2359296
#define W2T_OFF 4718592
#define LSZ     7077888
#define WOUT_OFF (12*LSZ)
#define WTOT     (WOUT_OFF + (long)VQP*DQ)

// ---------------- static scratch ----------------
__device__ __align__(128) float    g_h   [NT*DQ];
__device__ __align__(128) float    g_q   [NT*DQ];
__device__ __align__(128) float    g_k   [NT*DQ];
__device__ __align__(128) float    g_v   [NT*DQ];
__device__ __align__(128) uint16_t g_hnh [NT*DQ],  g_hnl [NT*DQ];
__device__ __align__(128) uint16_t g_ctxh[NT*DQ],  g_ctxl[NT*DQ];
__device__ __align__(128) uint16_t g_ffh [NT*FFQ], g_ffl [NT*FFQ];
__device__ __align__(128) uint16_t g_wth [WTOT];   // fp16 W^T, single image

// ---------------- helpers ----------------
__device__ __forceinline__ float gelu_f(float x) {
    const float c = 0.7978845608028654f;
    float x3 = x * x * x;
    return 0.5f * x * (1.0f + tanhf(c * (x + 0.044715f * x3)));
}

__device__ __forceinline__ uint32_t smem_u32(const void* p) {
    uint32_t a;
    asm("{ .reg .u64 t; cvta.to.shared.u64 t, %1; cvt.u32.u64 %0, t; }" : "=r"(a) : "l"(p));
    return a;
}

// split fp32 pair -> packed hi-fp16x2 / lo-fp16x2
__device__ __forceinline__ void splith2(float a, float b, uint32_t& hi, uint32_t& lo) {
    __half ha = __float2half_rn(a), hb = __float2half_rn(b);
    float ra = a - __half2float(ha), rb = b - __half2float(hb);
    __half la = __float2half_rn(ra), lb = __float2half_rn(rb);
    hi = ((uint32_t)__half_as_ushort(hb) << 16) | (uint32_t)__half_as_ushort(ha);
    lo = ((uint32_t)__half_as_ushort(lb) << 16) | (uint32_t)__half_as_ushort(la);
}

__device__ __forceinline__ void ldsm4(uint32_t& r0, uint32_t& r1, uint32_t& r2, uint32_t& r3,
                                      uint32_t addr) {
    asm volatile("ldmatrix.sync.aligned.m8n8.x4.shared.b16 {%0,%1,%2,%3}, [%4];"
        : "=r"(r0), "=r"(r1), "=r"(r2), "=r"(r3) : "r"(addr));
}

__device__ __forceinline__ void mma_f16(float* c, const uint32_t* a, const uint32_t* b) {
    asm volatile("mma.sync.aligned.m16n8k16.row.col.f32.f16.f16.f32 "
        "{%0,%1,%2,%3}, {%4,%5,%6,%7}, {%8,%9}, {%0,%1,%2,%3};"
        : "+f"(c[0]), "+f"(c[1]), "+f"(c[2]), "+f"(c[3])
        : "r"(a[0]), "r"(a[1]), "r"(a[2]), "r"(a[3]), "r"(b[0]), "r"(b[1]));
}

__device__ __forceinline__ void cpa16(uint32_t saddr, const void* g) {
    asm volatile("cp.async.cg.shared.global [%0], [%1], 16;" :: "r"(saddr), "l"(g));
}

// ---------------- weight transpose + fp16 convert: W[K][N] fp32 -> T[N][K] fp16 ----------------
__global__ void gpt_wsplit(const float* __restrict__ W, uint16_t* __restrict__ Th,
                           int K, int N, int Npad, long ws, long ts) {
    int l = blockIdx.z;
    W  += (long)l * ws;
    Th += (long)l * ts;
    __shared__ float t[32][33];
    int n0 = blockIdx.x * 32, k0 = blockIdx.y * 32;
    int tx = threadIdx.x, ty = threadIdx.y;
    #pragma unroll
    for (int j = 0; j < 4; j++) {
        int n = n0 + tx;
        t[ty + j * 8][tx] = (n < N) ? W[(long)(k0 + ty + j * 8) * N + n] : 0.f;
    }
    __syncthreads();
    #pragma unroll
    for (int j = 0; j < 4; j++) {
        int n = n0 + ty + j * 8;
        if (n < Npad)
            Th[(long)n * K + k0 + tx] = __half_as_ushort(__float2half_rn(t[tx][ty + j * 8]));
    }
}

// ---------------- embedding ----------------
__global__ void gpt_embed(const int* __restrict__ x, const float* __restrict__ tok,
                          const float* __restrict__ pos, float* __restrict__ h) {
    int i = blockIdx.x * blockDim.x + threadIdx.x;
    if (i < NT * DQ) {
        int t = i / DQ, d = i - t * DQ;
        int s = t & (SQ - 1);
        h[i] = tok[(long)x[t] * DQ + d] + pos[s * DQ + d];
    }
}

// ---------------- layernorm -> fp16 hi/lo ----------------
__global__ void gpt_ln(const float* __restrict__ in, const float* __restrict__ scale,
                       const float* __restrict__ shift,
                       uint16_t* __restrict__ oh, uint16_t* __restrict__ ol) {
    int t = blockIdx.x;
    const float* row = in + (long)t * DQ;
    __shared__ float red[256];
    int tid = threadIdx.x;

    float s = 0.f;
    for (int d = tid; d < DQ; d += 256) s += row[d];
    red[tid] = s; __syncthreads();
    for (int o = 128; o > 0; o >>= 1) { if (tid < o) red[tid] += red[tid + o]; __syncthreads(); }
    float mean = red[0] * (1.0f / DQ); __syncthreads();

    float sq = 0.f;
    for (int d = tid; d < DQ; d += 256) { float v = row[d] - mean; sq += v * v; }
    red[tid] = sq; __syncthreads();
    for (int o = 128; o > 0; o >>= 1) { if (tid < o) red[tid] += red[tid + o]; __syncthreads(); }
    float inv = rsqrtf(red[0] * (1.0f / DQ) + 1e-5f);

    long base = (long)t * DQ;
    for (int d = tid; d < DQ; d += 256) {
        float v = scale[d] * (row[d] - mean) * inv + shift[d];
        __half hb = __float2half_rn(v);
        float r = v - __half2float(hb);
        oh[base + d] = __half_as_ushort(hb);
        ol[base + d] = __half_as_ushort(__float2half_rn(r));
    }
}

// ---------------- fp16x2 GEMM: A hi/lo fp16, B fp16, 2 MMA chains ----------------
// BM=64, BN=128, K chunk 32. stage: Ah(64 rows) | Al(64) | B(128), rows 80B.
// 3-stage cp.async pipeline, one __syncthreads per chunk, 2 CTAs/SM.
#define BM   64
#define OAL  5120
#define OB   10240
#define STG  20480

__device__ __forceinline__ void load_stage(uint32_t sst,
    const uint16_t* __restrict__ Ah, const uint16_t* __restrict__ Al,
    const uint16_t* __restrict__ B,
    int bm, int bn, int K, int c, int tid) {
    #pragma unroll
    for (int p = 0; p < 2; p++) {
        int idx = tid + p * 256;
        int row = idx >> 2, seg = idx & 3;
        long go = (long)row * K + c * 32 + seg * 8;
        cpa16(sst + OB + row * 80 + seg * 16, B + (long)bn * K + go);
    }
    {
        int row = tid >> 2, seg = tid & 3;
        long go = (long)(bm + row) * K + c * 32 + seg * 8;
        uint32_t so = row * 80 + seg * 16;
        cpa16(sst + so,       Ah + go);
        cpa16(sst + OAL + so, Al + go);
    }
    asm volatile("cp.async.commit_group;" ::: "memory");
}

__device__ __forceinline__ void mma_stage(uint32_t sst, float acc[2][4][4],
        int wm, int wn, int a_row, int a_kof, int b_nof, int b_kof) {
    #pragma unroll
    for (int kk = 0; kk < 32; kk += 16) {
        uint32_t fah[2][4], fal[2][4], fb[4][2];
        #pragma unroll
        for (int ma = 0; ma < 2; ma++) {
            uint32_t ro = (uint32_t)((wm * 32 + ma * 16 + a_row) * 80 + (kk + a_kof) * 2);
            ldsm4(fah[ma][0], fah[ma][1], fah[ma][2], fah[ma][3], sst + ro);
        }
        #pragma unroll
        for (int np = 0; np < 2; np++) {
            uint32_t ro = (uint32_t)((wn * 32 + np * 16 + b_nof) * 80 + (kk + b_kof) * 2);
            ldsm4(fb[2*np][0], fb[2*np][1], fb[2*np+1][0], fb[2*np+1][1], sst + OB + ro);
        }
        #pragma unroll
        for (int ma = 0; ma < 2; ma++)
            #pragma unroll
            for (int na = 0; na < 4; na++)
                mma_f16(acc[ma][na], fah[ma], fb[na]);
        #pragma unroll
        for (int ma = 0; ma < 2; ma++) {
            uint32_t ro = (uint32_t)((wm * 32 + ma * 16 + a_row) * 80 + (kk + a_kof) * 2);
            ldsm4(fal[ma][0], fal[ma][1], fal[ma][2], fal[ma][3], sst + OAL + ro);
        }
        #pragma unroll
        for (int ma = 0; ma < 2; ma++)
            #pragma unroll
            for (int na = 0; na < 4; na++)
                mma_f16(acc[ma][na], fal[ma], fb[na]);
    }
}

// EPI: 0 fp32 plain; 2 fp32 +bias+res; 3 gelu(x+bias)->fp16 hi/lo. NG: guard gn.
template<int EPI, bool NG>
__device__ __forceinline__ void bmma_core(
    const uint16_t* __restrict__ Ah, const uint16_t* __restrict__ Al,
    const uint16_t* __restrict__ B,
    const float* __restrict__ bias, const float* __restrict__ res,
    float* __restrict__ C, uint16_t* __restrict__ Ch, uint16_t* __restrict__ Cl,
    int Ntot, int K, int ldc, int miter) {
    extern __shared__ __align__(16) char smem[];
    uint32_t sb = smem_u32(smem);
    int tid = threadIdx.x;
    int lane = tid & 31, wid = tid >> 5;
    int wm = wid >> 2, wn = wid & 3;
    int bn = blockIdx.x * 128;

    int l8 = lane & 7;
    int a_row = ((lane >> 3) & 1) * 8 + l8;
    int a_kof = (lane >> 4) * 8;
    int b_nof = (lane >> 4) * 8 + l8;
    int b_kof = ((lane >> 3) & 1) * 8;
    int g = lane >> 2, tig = lane & 3;
    const int NCH = K >> 5;

    for (int mi = 0; mi < miter; mi++) {
        int bm = (blockIdx.y * miter + mi) * BM;
        if (mi) __syncthreads();   // all warps done with all buffers before refill

        float acc[2][4][4];
        #pragma unroll
        for (int i = 0; i < 2; i++)
            #pragma unroll
            for (int j = 0; j < 4; j++)
                #pragma unroll
                for (int r2 = 0; r2 < 4; r2++) acc[i][j][r2] = 0.f;

        load_stage(sb,       Ah, Al, B, bm, bn, K, 0, tid);
        load_stage(sb + STG, Ah, Al, B, bm, bn, K, 1, tid);

        for (int c = 0; c < NCH; c++) {
            if (c + 1 < NCH) {
                asm volatile("cp.async.wait_group 1;" ::: "memory");
            } else {
                asm volatile("cp.async.wait_group 0;" ::: "memory");
            }
            __syncthreads();
            if (c + 2 < NCH)
                load_stage(sb + ((c + 2) % 3) * STG, Ah, Al, B, bm, bn, K, c + 2, tid);
            mma_stage(sb + (c % 3) * STG, acc, wm, wn, a_row, a_kof, b_nof, b_kof);
        }

        #pragma unroll
        for (int ma = 0; ma < 2; ma++) {
            int r0 = bm + wm * 32 + ma * 16 + g;
            #pragma unroll
            for (int na = 0; na < 4; na++) {
                int gn = bn + wn * 32 + na * 8 + 2 * tig;
                #pragma unroll
                for (int half = 0; half < 2; half++) {
                    int gm = r0 + half * 8;
                    float v0 = acc[ma][na][half * 2 + 0];
                    float v1 = acc[ma][na][half * 2 + 1];
                    long gi = (long)gm * ldc + gn;
                    if (NG) {
                        if (gn < Ntot)     C[gi]     = v0;
                        if (gn + 1 < Ntot) C[gi + 1] = v1;
                    } else if (EPI == 3) {
                        v0 = gelu_f(v0 + bias[gn]);
                        v1 = gelu_f(v1 + bias[gn + 1]);
                        uint32_t hh, ll;
                        splith2(v0, v1, hh, ll);
                        *(uint32_t*)&Ch[gi] = hh;
                        *(uint32_t*)&Cl[gi] = ll;
                    } else {
                        if (EPI == 2) {
                            v0 += bias[gn]     + res[gi];
                            v1 += bias[gn + 1] + res[gi + 1];
                        }
                        *(float2*)&C[gi] = make_float2(v0, v1);
                    }
                }
            }
        }
    }
}

template<int EPI, bool NG>
__global__ void __launch_bounds__(256, 2)
gpt_bmma(const uint16_t* __restrict__ Ah, const uint16_t* __restrict__ Al,
         const uint16_t* __restrict__ B,
         const float* __restrict__ bias, const float* __restrict__ res,
         float* __restrict__ C, uint16_t* __restrict__ Ch, uint16_t* __restrict__ Cl,
         int Ntot, int K, int ldc, int miter) {
    bmma_core<EPI, NG>(Ah, Al, B, bias, res, C, Ch, Cl, Ntot, K, ldc, miter);
}

__global__ void __launch_bounds__(256, 2)
gpt_bmma_qkv(const uint16_t* __restrict__ Ah, const uint16_t* __restrict__ Al,
             const uint16_t* __restrict__ Wt,
             float* __restrict__ Oq, float* __restrict__ Ok, float* __restrict__ Ov) {
    int z = blockIdx.z;
    const uint16_t* B = Wt + (long)z * 589824;
    float* C = (z == 0) ? Oq : (z == 1) ? Ok : Ov;
    bmma_core<0, false>(Ah, Al, B, nullptr, nullptr, C, nullptr, nullptr, DQ, DQ, DQ, 1);
}

// ---------------- fused flash attention (epilogue -> fp16 hi/lo ctx) ----------------
__global__ void __launch_bounds__(256, 2)
gpt_flash(const float* __restrict__ Q, const float* __restrict__ Kx,
          const float* __restrict__ Vx,
          uint16_t* __restrict__ ctxh, uint16_t* __restrict__ ctxl) {
    extern __shared__ float sm[];
    float* Qs   = sm;
    float* Ks   = sm + 4096;
    float* Vs   = sm + 8192;
    float* rowm = sm + 12288;
    float* rowl = rowm + 64;
    float* rowf = rowm + 128;

    int z = blockIdx.y;
    int b = z / HQ, h = z - b * HQ;
    int qt = blockIdx.x, q0 = qt * 64;
    int tid = threadIdx.x;
    int r = tid & 63, dg = tid >> 6;
    int ty = tid >> 4, tx = tid & 15;

    {
        const float* qrow = Q + ((long)(b * SQ + q0 + r)) * DQ + h * HDQ + dg * 16;
        #pragma unroll
        for (int i = 0; i < 4; i++) {
            float4 t = *(const float4*)(qrow + i * 4);
            int d = dg * 16 + i * 4;
            Qs[(d + 0) * 64 + r] = t.x; Qs[(d + 1) * 64 + r] = t.y;
            Qs[(d + 2) * 64 + r] = t.z; Qs[(d + 3) * 64 + r] = t.w;
        }
    }
    if (tid < 64) { rowm[tid] = -1e30f; rowl[tid] = 0.f; }

    float o[4][4] = {};

    for (int j = 0; j <= qt; j++) {
        int k0 = j * 64;
        __syncthreads();
        {
            const float* krow = Kx + ((long)(b * SQ + k0 + r)) * DQ + h * HDQ + dg * 16;
            const float* vrow = Vx + ((long)(b * SQ + k0 + r)) * DQ + h * HDQ + dg * 16;
            #pragma unroll
            for (int i = 0; i < 4; i++) {
                float4 t = *(const float4*)(krow + i * 4);
                int d = dg * 16 + i * 4;
                Ks[(d + 0) * 64 + r] = t.x; Ks[(d + 1) * 64 + r] = t.y;
                Ks[(d + 2) * 64 + r] = t.z; Ks[(d + 3) * 64 + r] = t.w;
                float4 tv = *(const float4*)(vrow + i * 4);
                *(float4*)&Vs[r * 64 + dg * 16 + i * 4] = tv;
            }
        }
        __syncthreads();

        float s[4][4] = {};
        #pragma unroll 8
        for (int d = 0; d < 64; d++) {
            float qv[4], kv[4];
            #pragma unroll
            for (int i = 0; i < 4; i++) qv[i] = Qs[d * 64 + ty * 4 + i];
            #pragma unroll
            for (int c = 0; c < 4; c++) kv[c] = Ks[d * 64 + tx * 4 + c];
            #pragma unroll
            for (int i = 0; i < 4; i++)
                #pragma unroll
                for (int c = 0; c < 4; c++)
                    s[i][c] += qv[i] * kv[c];
        }
        #pragma unroll
        for (int i = 0; i < 4; i++)
            #pragma unroll
            for (int c = 0; c < 4; c++) {
                s[i][c] *= 0.125f;
                if (j == qt && (k0 + tx * 4 + c) > (q0 + ty * 4 + i)) s[i][c] = -1e30f;
            }
        __syncthreads();
        #pragma unroll
        for (int i = 0; i < 4; i++)
            #pragma unroll
            for (int c = 0; c < 4; c++)
                Ks[(ty * 4 + i) * 64 + tx * 4 + c] = s[i][c];
        __syncthreads();

        if (tid < 64) {
            float m_old = rowm[tid], m = m_old;
            #pragma unroll 8
            for (int t = 0; t < 64; t++) {
                int kk = (t + tid) & 63;
                m = fmaxf(m, Ks[tid * 64 + kk]);
            }
            float f = __expf(m_old - m);
            float l = rowl[tid] * f;
            #pragma unroll 8
            for (int t = 0; t < 64; t++) {
                int kk = (t + tid) & 63;
                float p = __expf(Ks[tid * 64 + kk] - m);
                Ks[tid * 64 + kk] = p;
                l += p;
            }
            rowm[tid] = m; rowl[tid] = l; rowf[tid] = f;
        }
        __syncthreads();

        float fr[4];
        #pragma unroll
        for (int i = 0; i < 4; i++) fr[i] = rowf[ty * 4 + i];
        #pragma unroll
        for (int i = 0; i < 4; i++)
            #pragma unroll
            for (int c = 0; c < 4; c++) o[i][c] *= fr[i];
        #pragma unroll 8
        for (int kk = 0; kk < 64; kk++) {
            float p[4];
            #pragma unroll
            for (int i = 0; i < 4; i++) p[i] = Ks[(ty * 4 + i) * 64 + kk];
            float4 vv = *(const float4*)&Vs[kk * 64 + tx * 4];
            #pragma unroll
            for (int i = 0; i < 4; i++) {
                o[i][0] += p[i] * vv.x; o[i][1] += p[i] * vv.y;
                o[i][2] += p[i] * vv.z; o[i][3] += p[i] * vv.w;
            }
        }
    }

    #pragma unroll
    for (int i = 0; i < 4; i++) {
        float inv = 1.0f / rowl[ty * 4 + i];
        float v0 = o[i][0] * inv, v1 = o[i][1] * inv;
        float v2 = o[i][2] * inv, v3 = o[i][3] * inv;
        uint32_t h01, l01, h23, l23;
        splith2(v0, v1, h01, l01);
        splith2(v2, v3, h23, l23);
        long base = ((long)(b * SQ + q0 + ty * 4 + i)) * DQ + h * HDQ + tx * 4;
        *(uint2*)&ctxh[base] = make_uint2(h01, h23);
        *(uint2*)&ctxl[base] = make_uint2(l01, l23);
    }
}

// ---------------- host orchestration ----------------
extern "C" void kernel_launch(void* const* d_in, const int* in_sizes, int n_in,
                              void* d_out, int out_size) {
    const int*   x    = (const int*)  d_in[0];
    const float* tok  = (const float*)d_in[1];
    const float* pos  = (const float*)d_in[2];
    const float* ln1s = (const float*)d_in[3];
    const float* ln1b = (const float*)d_in[4];
    const float* wq   = (const float*)d_in[5];
    const float* wk   = (const float*)d_in[6];
    const float* wv   = (const float*)d_in[7];
    const float* wo   = (const float*)d_in[8];
    const float* bo   = (const float*)d_in[9];
    const float* ln2s = (const float*)d_in[10];
    const float* ln2b = (const float*)d_in[11];
    const float* w1   = (const float*)d_in[12];
    const float* b1   = (const float*)d_in[13];
    const float* w2   = (const float*)d_in[14];
    const float* b2   = (const float*)d_in[15];
    const float* fs   = (const float*)d_in[16];
    const float* fb   = (const float*)d_in[17];
    const float* wout = (const float*)d_in[18];
    float* out = (float*)d_out;

    float *h, *q, *k, *v;
    uint16_t *hnh, *hnl, *ctxh, *ctxl, *ffh, *ffl, *wth;
    cudaGetSymbolAddress((void**)&h,    g_h);
    cudaGetSymbolAddress((void**)&q,    g_q);
    cudaGetSymbolAddress((void**)&k,    g_k);
    cudaGetSymbolAddress((void**)&v,    g_v);
    cudaGetSymbolAddress((void**)&hnh,  g_hnh);
    cudaGetSymbolAddress((void**)&hnl,  g_hnl);
    cudaGetSymbolAddress((void**)&ctxh, g_ctxh);
    cudaGetSymbolAddress((void**)&ctxl, g_ctxl);
    cudaGetSymbolAddress((void**)&ffh,  g_ffh);
    cudaGetSymbolAddress((void**)&ffl,  g_ffl);
    cudaGetSymbolAddress((void**)&wth,  g_wth);

    const int FLASH_SMEM = (64 * 64 * 3 + 64 * 3) * sizeof(float); // 49920
    const int GSMEM = 3 * STG;                                      // 61440
    cudaFuncSetAttribute(gpt_flash, cudaFuncAttributeMaxDynamicSharedMemorySize, FLASH_SMEM);
    cudaFuncSetAttribute((const void*)gpt_bmma<2, false>, cudaFuncAttributeMaxDynamicSharedMemorySize, GSMEM);
    cudaFuncSetAttribute((const void*)gpt_bmma<3, false>, cudaFuncAttributeMaxDynamicSharedMemorySize, GSMEM);
    cudaFuncSetAttribute((const void*)gpt_bmma<0, true>,  cudaFuncAttributeMaxDynamicSharedMemorySize, GSMEM);
    cudaFuncSetAttribute((const void*)gpt_bmma_qkv,       cudaFuncAttributeMaxDynamicSharedMemorySize, GSMEM);

    // ---- weight transpose + fp16 convert, batched over layers ----
    dim3 wt(32, 8);
    gpt_wsplit<<<dim3(24, 24, 12), wt>>>(wq,  wth + WQ_OFF,  DQ, DQ, DQ,  (long)DQ*DQ,  (long)LSZ);
    gpt_wsplit<<<dim3(24, 24, 12), wt>>>(wk,  wth + WK_OFF,  DQ, DQ, DQ,  (long)DQ*DQ,  (long)LSZ);
    gpt_wsplit<<<dim3(24, 24, 12), wt>>>(wv,  wth + WV_OFF,  DQ, DQ, DQ,  (long)DQ*DQ,  (long)LSZ);
    gpt_wsplit<<<dim3(24, 24, 12), wt>>>(wo,  wth + WO_OFF,  DQ, DQ, DQ,  (long)DQ*DQ,  (long)LSZ);
    gpt_wsplit<<<dim3(96, 24, 12), wt>>>(w1,  wth + W1T_OFF, DQ, FFQ, FFQ, (long)DQ*FFQ, (long)LSZ);
    gpt_wsplit<<<dim3(24, 96, 12), wt>>>(w2,  wth + W2T_OFF, FFQ, DQ, DQ,  (long)FFQ*DQ, (long)LSZ);
    gpt_wsplit<<<dim3(VQP / 32, 24, 1), wt>>>(wout, wth + WOUT_OFF, DQ, VQ, VQP, 0, 0);

    gpt_embed<<<(NT * DQ + 255) / 256, 256>>>(x, tok, pos, h);

    dim3 gP (DQ / 128,  NT / 64);         // (6,32)
    dim3 gQ (DQ / 128,  NT / 64, 3);      // (6,32,3)
    dim3 gF1(FFQ / 128, NT / 64);         // (24,32)
    dim3 gV (VQP / 128, 8);               // (393,8) miter=4
    dim3 gFl(SQ / 64,   BQ * HQ);         // (8,48)

    for (int l = 0; l < LQ; l++) {
        long lo = (long)l * LSZ;

        gpt_ln<<<NT, 256>>>(h, ln1s + l * DQ, ln1b + l * DQ, hnh, hnl);

        gpt_bmma_qkv<<<gQ, 256, GSMEM>>>(hnh, hnl, wth + lo + WQ_OFF, q, k, v);

        gpt_flash<<<gFl, 256, FLASH_SMEM>>>(q, k, v, ctxh, ctxl);

        gpt_bmma<2, false><<<gP, 256, GSMEM>>>(ctxh, ctxl,
            wth + lo + WO_OFF, bo + l * DQ, h, h, nullptr, nullptr, DQ, DQ, DQ, 1);

        gpt_ln<<<NT, 256>>>(h, ln2s + l * DQ, ln2b + l * DQ, hnh, hnl);

        gpt_bmma<3, false><<<gF1, 256, GSMEM>>>(hnh, hnl,
            wth + lo + W1T_OFF, b1 + l * FFQ, nullptr, nullptr, ffh, ffl, FFQ, DQ, FFQ, 1);

        gpt_bmma<2, false><<<gP, 256, GSMEM>>>(ffh, ffl,
            wth + lo + W2T_OFF, b2 + l * DQ, h, h, nullptr, nullptr, DQ, FFQ, DQ, 1);
    }

    gpt_ln<<<NT, 256>>>(h, fs, fb, hnh, hnl);

    gpt_bmma<0, true><<<gV, 256, GSMEM>>>(hnh, hnl,
        wth + WOUT_OFF, nullptr, nullptr, out, nullptr, nullptr, VQ, DQ, VQ, 4);
}

// round 12
// speedup vs baseline: 1.5018x; 1.2223x over previous
#include <cuda_runtime.h>
#include <cuda_fp16.h>
#include <math.h>
#include <stdint.h>

// ---------------- problem constants ----------------
#define BQ   4
#define SQ   512
#define DQ   768
#define HQ   12
#define HDQ  64
#define LQ   12
#define VQ   50257
#define VQP  50304
#define FFQ  3072
#define NT   (BQ*SQ)

#define WQ_OFF  0
#define WK_OFF  589824
#define WV_OFF  1179648
#define WO_OFF  1769472
#define W1T_OFF 2359296
#define W2T_OFF 4718592
#define LSZ     7077888
#define WOUT_OFF (12*LSZ)
#define WTOT     (WOUT_OFF + (long)VQP*DQ)

// ---------------- static scratch ----------------
__device__ __align__(128) float    g_h   [NT*DQ];
__device__ __align__(128) float    g_q   [NT*DQ];
__device__ __align__(128) float    g_k   [NT*DQ];
__device__ __align__(128) float    g_v   [NT*DQ];
__device__ __align__(128) uint16_t g_hnh [NT*DQ],  g_hnl [NT*DQ];
__device__ __align__(128) uint16_t g_ctxh[NT*DQ],  g_ctxl[NT*DQ];
__device__ __align__(128) uint16_t g_ffh [NT*FFQ], g_ffl [NT*FFQ];
__device__ __align__(128) uint16_t g_wth [WTOT];   // fp16 W^T, single image

// ---------------- helpers ----------------
__device__ __forceinline__ float gelu_f(float x) {
    const float c = 0.7978845608028654f;
    float x3 = x * x * x;
    return 0.5f * x * (1.0f + tanhf(c * (x + 0.044715f * x3)));
}

__device__ __forceinline__ uint32_t smem_u32(const void* p) {
    uint32_t a;
    asm("{ .reg .u64 t; cvta.to.shared.u64 t, %1; cvt.u32.u64 %0, t; }" : "=r"(a) : "l"(p));
    return a;
}

__device__ __forceinline__ void splith2(float a, float b, uint32_t& hi, uint32_t& lo) {
    __half ha = __float2half_rn(a), hb = __float2half_rn(b);
    float ra = a - __half2float(ha), rb = b - __half2float(hb);
    __half la = __float2half_rn(ra), lb = __float2half_rn(rb);
    hi = ((uint32_t)__half_as_ushort(hb) << 16) | (uint32_t)__half_as_ushort(ha);
    lo = ((uint32_t)__half_as_ushort(lb) << 16) | (uint32_t)__half_as_ushort(la);
}

__device__ __forceinline__ uint32_t packh2(float a, float b) {
    __half2 h = __float22half2_rn(make_float2(a, b));
    return *(uint32_t*)&h;
}

__device__ __forceinline__ void ldsm4(uint32_t& r0, uint32_t& r1, uint32_t& r2, uint32_t& r3,
                                      uint32_t addr) {
    asm volatile("ldmatrix.sync.aligned.m8n8.x4.shared.b16 {%0,%1,%2,%3}, [%4];"
        : "=r"(r0), "=r"(r1), "=r"(r2), "=r"(r3) : "r"(addr));
}

__device__ __forceinline__ void ldsm4t(uint32_t& r0, uint32_t& r1, uint32_t& r2, uint32_t& r3,
                                       uint32_t addr) {
    asm volatile("ldmatrix.sync.aligned.m8n8.x4.trans.shared.b16 {%0,%1,%2,%3}, [%4];"
        : "=r"(r0), "=r"(r1), "=r"(r2), "=r"(r3) : "r"(addr));
}

__device__ __forceinline__ void mma_f16(float* c, const uint32_t* a, const uint32_t* b) {
    asm volatile("mma.sync.aligned.m16n8k16.row.col.f32.f16.f16.f32 "
        "{%0,%1,%2,%3}, {%4,%5,%6,%7}, {%8,%9}, {%0,%1,%2,%3};"
        : "+f"(c[0]), "+f"(c[1]), "+f"(c[2]), "+f"(c[3])
        : "r"(a[0]), "r"(a[1]), "r"(a[2]), "r"(a[3]), "r"(b[0]), "r"(b[1]));
}

__device__ __forceinline__ void cpa16(uint32_t saddr, const void* g) {
    asm volatile("cp.async.cg.shared.global [%0], [%1], 16;" :: "r"(saddr), "l"(g));
}

// ---------------- weight transpose + fp16 convert ----------------
__global__ void gpt_wsplit(const float* __restrict__ W, uint16_t* __restrict__ Th,
                           int K, int N, int Npad, long ws, long ts) {
    int l = blockIdx.z;
    W  += (long)l * ws;
    Th += (long)l * ts;
    __shared__ float t[32][33];
    int n0 = blockIdx.x * 32, k0 = blockIdx.y * 32;
    int tx = threadIdx.x, ty = threadIdx.y;
    #pragma unroll
    for (int j = 0; j < 4; j++) {
        int n = n0 + tx;
        t[ty + j * 8][tx] = (n < N) ? W[(long)(k0 + ty + j * 8) * N + n] : 0.f;
    }
    __syncthreads();
    #pragma unroll
    for (int j = 0; j < 4; j++) {
        int n = n0 + ty + j * 8;
        if (n < Npad)
            Th[(long)n * K + k0 + tx] = __half_as_ushort(__float2half_rn(t[tx][ty + j * 8]));
    }
}

// ---------------- embedding ----------------
__global__ void gpt_embed(const int* __restrict__ x, const float* __restrict__ tok,
                          const float* __restrict__ pos, float* __restrict__ h) {
    int i = blockIdx.x * blockDim.x + threadIdx.x;
    if (i < NT * DQ) {
        int t = i / DQ, d = i - t * DQ;
        int s = t & (SQ - 1);
        h[i] = tok[(long)x[t] * DQ + d] + pos[s * DQ + d];
    }
}

// ---------------- layernorm: single pass, one sync ----------------
__global__ void gpt_ln(const float* __restrict__ in, const float* __restrict__ scale,
                       const float* __restrict__ shift,
                       uint16_t* __restrict__ oh, uint16_t* __restrict__ ol) {
    int t = blockIdx.x;
    const float* row = in + (long)t * DQ;
    int tid = threadIdx.x, lane = tid & 31, wid = tid >> 5;
    __shared__ float ws[8], wss[8];

    float x0 = row[tid], x1 = row[tid + 256], x2 = row[tid + 512];
    float s = x0 + x1 + x2;
    float ss = x0 * x0 + x1 * x1 + x2 * x2;
    #pragma unroll
    for (int o = 16; o > 0; o >>= 1) {
        s  += __shfl_xor_sync(0xffffffffu, s,  o);
        ss += __shfl_xor_sync(0xffffffffu, ss, o);
    }
    if (lane == 0) { ws[wid] = s; wss[wid] = ss; }
    __syncthreads();
    float S = 0.f, SS = 0.f;
    #pragma unroll
    for (int i = 0; i < 8; i++) { S += ws[i]; SS += wss[i]; }
    float mean = S * (1.0f / DQ);
    float inv = rsqrtf(SS * (1.0f / DQ) - mean * mean + 1e-5f);

    long base = (long)t * DQ;
    #pragma unroll
    for (int p = 0; p < 3; p++) {
        int d = tid + p * 256;
        float xv = (p == 0) ? x0 : (p == 1) ? x1 : x2;
        float v = scale[d] * (xv - mean) * inv + shift[d];
        __half hb = __float2half_rn(v);
        float r = v - __half2float(hb);
        oh[base + d] = __half_as_ushort(hb);
        ol[base + d] = __half_as_ushort(__float2half_rn(r));
    }
}

// ---------------- fp16x2 GEMM (unchanged from R11 winner) ----------------
#define BM   64
#define OAL  5120
#define OB   10240
#define STG  20480

__device__ __forceinline__ void load_stage(uint32_t sst,
    const uint16_t* __restrict__ Ah, const uint16_t* __restrict__ Al,
    const uint16_t* __restrict__ B,
    int bm, int bn, int K, int c, int tid) {
    #pragma unroll
    for (int p = 0; p < 2; p++) {
        int idx = tid + p * 256;
        int row = idx >> 2, seg = idx & 3;
        long go = (long)row * K + c * 32 + seg * 8;
        cpa16(sst + OB + row * 80 + seg * 16, B + (long)bn * K + go);
    }
    {
        int row = tid >> 2, seg = tid & 3;
        long go = (long)(bm + row) * K + c * 32 + seg * 8;
        uint32_t so = row * 80 + seg * 16;
        cpa16(sst + so,       Ah + go);
        cpa16(sst + OAL + so, Al + go);
    }
    asm volatile("cp.async.commit_group;" ::: "memory");
}

__device__ __forceinline__ void mma_stage(uint32_t sst, float acc[2][4][4],
        int wm, int wn, int a_row, int a_kof, int b_nof, int b_kof) {
    #pragma unroll
    for (int kk = 0; kk < 32; kk += 16) {
        uint32_t fah[2][4], fal[2][4], fb[4][2];
        #pragma unroll
        for (int ma = 0; ma < 2; ma++) {
            uint32_t ro = (uint32_t)((wm * 32 + ma * 16 + a_row) * 80 + (kk + a_kof) * 2);
            ldsm4(fah[ma][0], fah[ma][1], fah[ma][2], fah[ma][3], sst + ro);
        }
        #pragma unroll
        for (int np = 0; np < 2; np++) {
            uint32_t ro = (uint32_t)((wn * 32 + np * 16 + b_nof) * 80 + (kk + b_kof) * 2);
            ldsm4(fb[2*np][0], fb[2*np][1], fb[2*np+1][0], fb[2*np+1][1], sst + OB + ro);
        }
        #pragma unroll
        for (int ma = 0; ma < 2; ma++)
            #pragma unroll
            for (int na = 0; na < 4; na++)
                mma_f16(acc[ma][na], fah[ma], fb[na]);
        #pragma unroll
        for (int ma = 0; ma < 2; ma++) {
            uint32_t ro = (uint32_t)((wm * 32 + ma * 16 + a_row) * 80 + (kk + a_kof) * 2);
            ldsm4(fal[ma][0], fal[ma][1], fal[ma][2], fal[ma][3], sst + OAL + ro);
        }
        #pragma unroll
        for (int ma = 0; ma < 2; ma++)
            #pragma unroll
            for (int na = 0; na < 4; na++)
                mma_f16(acc[ma][na], fal[ma], fb[na]);
    }
}

template<int EPI, bool NG>
__device__ __forceinline__ void bmma_core(
    const uint16_t* __restrict__ Ah, const uint16_t* __restrict__ Al,
    const uint16_t* __restrict__ B,
    const float* __restrict__ bias, const float* __restrict__ res,
    float* __restrict__ C, uint16_t* __restrict__ Ch, uint16_t* __restrict__ Cl,
    int Ntot, int K, int ldc, int miter) {
    extern __shared__ __align__(16) char smem[];
    uint32_t sb = smem_u32(smem);
    int tid = threadIdx.x;
    int lane = tid & 31, wid = tid >> 5;
    int wm = wid >> 2, wn = wid & 3;
    int bn = blockIdx.x * 128;

    int l8 = lane & 7;
    int a_row = ((lane >> 3) & 1) * 8 + l8;
    int a_kof = (lane >> 4) * 8;
    int b_nof = (lane >> 4) * 8 + l8;
    int b_kof = ((lane >> 3) & 1) * 8;
    int g = lane >> 2, tig = lane & 3;
    const int NCH = K >> 5;

    for (int mi = 0; mi < miter; mi++) {
        int bm = (blockIdx.y * miter + mi) * BM;
        if (mi) __syncthreads();

        float acc[2][4][4];
        #pragma unroll
        for (int i = 0; i < 2; i++)
            #pragma unroll
            for (int j = 0; j < 4; j++)
                #pragma unroll
                for (int r2 = 0; r2 < 4; r2++) acc[i][j][r2] = 0.f;

        load_stage(sb,       Ah, Al, B, bm, bn, K, 0, tid);
        load_stage(sb + STG, Ah, Al, B, bm, bn, K, 1, tid);

        for (int c = 0; c < NCH; c++) {
            if (c + 1 < NCH) {
                asm volatile("cp.async.wait_group 1;" ::: "memory");
            } else {
                asm volatile("cp.async.wait_group 0;" ::: "memory");
            }
            __syncthreads();
            if (c + 2 < NCH)
                load_stage(sb + ((c + 2) % 3) * STG, Ah, Al, B, bm, bn, K, c + 2, tid);
            mma_stage(sb + (c % 3) * STG, acc, wm, wn, a_row, a_kof, b_nof, b_kof);
        }

        #pragma unroll
        for (int ma = 0; ma < 2; ma++) {
            int r0 = bm + wm * 32 + ma * 16 + g;
            #pragma unroll
            for (int na = 0; na < 4; na++) {
                int gn = bn + wn * 32 + na * 8 + 2 * tig;
                #pragma unroll
                for (int half = 0; half < 2; half++) {
                    int gm = r0 + half * 8;
                    float v0 = acc[ma][na][half * 2 + 0];
                    float v1 = acc[ma][na][half * 2 + 1];
                    long gi = (long)gm * ldc + gn;
                    if (NG) {
                        if (gn < Ntot)     C[gi]     = v0;
                        if (gn + 1 < Ntot) C[gi + 1] = v1;
                    } else if (EPI == 3) {
                        v0 = gelu_f(v0 + bias[gn]);
                        v1 = gelu_f(v1 + bias[gn + 1]);
                        uint32_t hh, ll;
                        splith2(v0, v1, hh, ll);
                        *(uint32_t*)&Ch[gi] = hh;
                        *(uint32_t*)&Cl[gi] = ll;
                    } else {
                        if (EPI == 2) {
                            v0 += bias[gn]     + res[gi];
                            v1 += bias[gn + 1] + res[gi + 1];
                        }
                        *(float2*)&C[gi] = make_float2(v0, v1);
                    }
                }
            }
        }
    }
}

template<int EPI, bool NG>
__global__ void __launch_bounds__(256, 2)
gpt_bmma(const uint16_t* __restrict__ Ah, const uint16_t* __restrict__ Al,
         const uint16_t* __restrict__ B,
         const float* __restrict__ bias, const float* __restrict__ res,
         float* __restrict__ C, uint16_t* __restrict__ Ch, uint16_t* __restrict__ Cl,
         int Ntot, int K, int ldc, int miter) {
    bmma_core<EPI, NG>(Ah, Al, B, bias, res, C, Ch, Cl, Ntot, K, ldc, miter);
}

__global__ void __launch_bounds__(256, 2)
gpt_bmma_qkv(const uint16_t* __restrict__ Ah, const uint16_t* __restrict__ Al,
             const uint16_t* __restrict__ Wt,
             float* __restrict__ Oq, float* __restrict__ Ok, float* __restrict__ Ov) {
    int z = blockIdx.z;
    const uint16_t* B = Wt + (long)z * 589824;
    float* C = (z == 0) ? Oq : (z == 1) ? Ok : Ov;
    bmma_core<0, false>(Ah, Al, B, nullptr, nullptr, C, nullptr, nullptr, DQ, DQ, DQ, 1);
}

// ---------------- tensor-core flash attention ----------------
// grid (8, 48), 256 thr, 8 warps = 4(m) x 2(n). 64q x 64kt tiles.
// Q hi/lo fp16 x K fp16 -> S fp32; online softmax; P hi/lo (from regs) x V fp16 -> O fp32.
#define FSTR 72
#define FOQH 0
#define FOQL 9216
#define FOKS 18432
#define FOVS 27648
#define FOOS 36864           // Osum 64*66 floats = 16896 B
#define FOST 53760           // stats: rowm,rowl,rowf,mnew (64 ea), pm[128], ps[128]
#define FLASH_SMEM 55808

__global__ void __launch_bounds__(256, 2)
gpt_flash(const float* __restrict__ Q, const float* __restrict__ Kx,
          const float* __restrict__ Vx,
          uint16_t* __restrict__ ctxh, uint16_t* __restrict__ ctxl) {
    extern __shared__ __align__(16) char fsm[];
    uint32_t sb = smem_u32(fsm);
    float* Osum = (float*)(fsm + FOOS);
    float* rowm = (float*)(fsm + FOST);
    float* rowl = rowm + 64;
    float* rowf = rowm + 128;
    float* mnew = rowm + 192;
    float* pm   = rowm + 256;   // [2][64]
    float* ps   = rowm + 384;   // [2][64]

    int z = blockIdx.y;
    int b = z / HQ, h = z - b * HQ;
    int qt = blockIdx.x, q0 = qt * 64;
    int tid = threadIdx.x, lane = tid & 31, wid = tid >> 5;
    int wm = wid >> 1, wn = wid & 1;
    int r = tid & 63, dg = tid >> 6;

    int l8 = lane & 7;
    int a_row = ((lane >> 3) & 1) * 8 + l8;
    int a_kof = (lane >> 4) * 8;
    int b_nof = (lane >> 4) * 8 + l8;
    int b_kof = ((lane >> 3) & 1) * 8;
    int bt_row = ((lane >> 3) & 1) * 8 + l8;   // k index for trans-B
    int bt_col = (lane >> 4) * 8;              // n index for trans-B
    int g = lane >> 2, tig = lane & 3;
    int row0 = wm * 16 + g;                    // local q rows row0, row0+8

    // load Q tile -> Qh/Ql fp16, [q][d] stride FSTR
    {
        const float* qrow = Q + ((long)(b * SQ + q0 + r)) * DQ + h * HDQ + dg * 16;
        uint16_t* Qh = (uint16_t*)fsm;
        uint16_t* Ql = (uint16_t*)(fsm + FOQL);
        #pragma unroll
        for (int i = 0; i < 4; i++) {
            float4 t = *(const float4*)(qrow + i * 4);
            uint32_t h01, l01, h23, l23;
            splith2(t.x, t.y, h01, l01);
            splith2(t.z, t.w, h23, l23);
            int off = r * FSTR + dg * 16 + i * 4;
            *(uint2*)&Qh[off] = make_uint2(h01, h23);
            *(uint2*)&Ql[off] = make_uint2(l01, l23);
        }
    }
    if (tid < 64) { rowm[tid] = -1e30f; rowl[tid] = 0.f; }

    float o[8][4];
    #pragma unroll
    for (int i = 0; i < 8; i++)
        #pragma unroll
        for (int j2 = 0; j2 < 4; j2++) o[i][j2] = 0.f;

    for (int j = 0; j <= qt; j++) {
        int k0 = j * 64;
        __syncthreads();
        {
            const float* krow = Kx + ((long)(b * SQ + k0 + r)) * DQ + h * HDQ + dg * 16;
            const float* vrow = Vx + ((long)(b * SQ + k0 + r)) * DQ + h * HDQ + dg * 16;
            uint16_t* Ks = (uint16_t*)(fsm + FOKS);
            uint16_t* Vs = (uint16_t*)(fsm + FOVS);
            #pragma unroll
            for (int i = 0; i < 4; i++) {
                float4 t = *(const float4*)(krow + i * 4);
                float4 tv = *(const float4*)(vrow + i * 4);
                int off = r * FSTR + dg * 16 + i * 4;
                *(uint2*)&Ks[off] = make_uint2(packh2(t.x, t.y), packh2(t.z, t.w));
                *(uint2*)&Vs[off] = make_uint2(packh2(tv.x, tv.y), packh2(tv.z, tv.w));
            }
        }
        __syncthreads();

        // S = Q K^T
        float s[4][4];
        #pragma unroll
        for (int na = 0; na < 4; na++)
            #pragma unroll
            for (int v2 = 0; v2 < 4; v2++) s[na][v2] = 0.f;
        #pragma unroll
        for (int kk = 0; kk < 64; kk += 16) {
            uint32_t fah[4], fal[4], fb[4][2];
            uint32_t aro = (uint32_t)((wm * 16 + a_row) * FSTR + kk + a_kof) * 2;
            ldsm4(fah[0], fah[1], fah[2], fah[3], sb + FOQH + aro);
            ldsm4(fal[0], fal[1], fal[2], fal[3], sb + FOQL + aro);
            #pragma unroll
            for (int np = 0; np < 2; np++) {
                uint32_t ro = (uint32_t)((wn * 32 + np * 16 + b_nof) * FSTR + kk + b_kof) * 2;
                ldsm4(fb[2*np][0], fb[2*np][1], fb[2*np+1][0], fb[2*np+1][1], sb + FOKS + ro);
            }
            #pragma unroll
            for (int na = 0; na < 4; na++) mma_f16(s[na], fah, fb[na]);
            #pragma unroll
            for (int na = 0; na < 4; na++) mma_f16(s[na], fal, fb[na]);
        }
        // scale + causal mask
        #pragma unroll
        for (int na = 0; na < 4; na++)
            #pragma unroll
            for (int v2 = 0; v2 < 4; v2++) {
                s[na][v2] *= 0.125f;
                if (j == qt) {
                    int kc = wn * 32 + na * 8 + 2 * tig + (v2 & 1);
                    int qr = row0 + (v2 >> 1) * 8;
                    if (kc > qr) s[na][v2] = -1e30f;
                }
            }
        // row max partials
        {
            float m0 = -1e30f, m1 = -1e30f;
            #pragma unroll
            for (int na = 0; na < 4; na++) {
                m0 = fmaxf(m0, fmaxf(s[na][0], s[na][1]));
                m1 = fmaxf(m1, fmaxf(s[na][2], s[na][3]));
            }
            m0 = fmaxf(m0, __shfl_xor_sync(0xffffffffu, m0, 1));
            m0 = fmaxf(m0, __shfl_xor_sync(0xffffffffu, m0, 2));
            m1 = fmaxf(m1, __shfl_xor_sync(0xffffffffu, m1, 1));
            m1 = fmaxf(m1, __shfl_xor_sync(0xffffffffu, m1, 2));
            if (tig == 0) { pm[wn * 64 + row0] = m0; pm[wn * 64 + row0 + 8] = m1; }
        }
        __syncthreads();
        if (tid < 64) {
            float mo = rowm[tid];
            float mn = fmaxf(mo, fmaxf(pm[tid], pm[64 + tid]));
            mnew[tid] = mn;
            rowf[tid] = __expf(mo - mn);
            rowm[tid] = mn;
        }
        __syncthreads();

        // exp, sums, P fragments
        uint32_t ah[2][4], al[2][4];
        {
            float mn0 = mnew[row0], mn1 = mnew[row0 + 8];
            float sum0 = 0.f, sum1 = 0.f;
            #pragma unroll
            for (int na = 0; na < 4; na++) {
                float p0 = __expf(s[na][0] - mn0);
                float p1 = __expf(s[na][1] - mn0);
                float p2 = __expf(s[na][2] - mn1);
                float p3 = __expf(s[na][3] - mn1);
                sum0 += p0 + p1; sum1 += p2 + p3;
                uint32_t h01, l01, h23, l23;
                splith2(p0, p1, h01, l01);
                splith2(p2, p3, h23, l23);
                int j2 = na >> 1;
                if ((na & 1) == 0) {
                    ah[j2][0] = h01; ah[j2][1] = h23;
                    al[j2][0] = l01; al[j2][1] = l23;
                } else {
                    ah[j2][2] = h01; ah[j2][3] = h23;
                    al[j2][2] = l01; al[j2][3] = l23;
                }
            }
            sum0 += __shfl_xor_sync(0xffffffffu, sum0, 1);
            sum0 += __shfl_xor_sync(0xffffffffu, sum0, 2);
            sum1 += __shfl_xor_sync(0xffffffffu, sum1, 1);
            sum1 += __shfl_xor_sync(0xffffffffu, sum1, 2);
            if (tig == 0) { ps[wn * 64 + row0] = sum0; ps[wn * 64 + row0 + 8] = sum1; }
        }
        __syncthreads();
        if (tid < 64) rowl[tid] = rowl[tid] * rowf[tid] + ps[tid] + ps[64 + tid];

        // rescale O, then PV
        {
            float f0 = rowf[row0], f1 = rowf[row0 + 8];
            #pragma unroll
            for (int nd = 0; nd < 8; nd++) {
                o[nd][0] *= f0; o[nd][1] *= f0;
                o[nd][2] *= f1; o[nd][3] *= f1;
            }
        }
        #pragma unroll
        for (int jj = 0; jj < 2; jj++) {
            uint32_t fbv[8][2];
            #pragma unroll
            for (int nb = 0; nb < 4; nb++) {
                uint32_t ro = (uint32_t)((wn * 32 + jj * 16 + bt_row) * FSTR + nb * 16 + bt_col) * 2;
                ldsm4t(fbv[2*nb][0], fbv[2*nb][1], fbv[2*nb+1][0], fbv[2*nb+1][1],
                       sb + FOVS + ro);
            }
            #pragma unroll
            for (int nd = 0; nd < 8; nd++) mma_f16(o[nd], ah[jj], fbv[nd]);
            #pragma unroll
            for (int nd = 0; nd < 8; nd++) mma_f16(o[nd], al[jj], fbv[nd]);
        }
    }

    // epilogue: combine wn halves, normalize, write fp16 hi/lo
    __syncthreads();
    if (wn == 0) {
        #pragma unroll
        for (int nd = 0; nd < 8; nd++)
            #pragma unroll
            for (int v2 = 0; v2 < 4; v2++)
                Osum[(row0 + (v2 >> 1) * 8) * 66 + nd * 8 + 2 * tig + (v2 & 1)] = o[nd][v2];
    }
    __syncthreads();
    if (wn == 1) {
        #pragma unroll
        for (int nd = 0; nd < 8; nd++)
            #pragma unroll
            for (int v2 = 0; v2 < 4; v2++)
                Osum[(row0 + (v2 >> 1) * 8) * 66 + nd * 8 + 2 * tig + (v2 & 1)] += o[nd][v2];
    }
    __syncthreads();
    {
        int orow = tid >> 2, c0 = (tid & 3) * 16;
        float inv = 1.0f / rowl[orow];
        uint32_t hv[8], lv[8];
        #pragma unroll
        for (int i = 0; i < 8; i++) {
            float v0 = Osum[orow * 66 + c0 + 2 * i]     * inv;
            float v1 = Osum[orow * 66 + c0 + 2 * i + 1] * inv;
            splith2(v0, v1, hv[i], lv[i]);
        }
        long base = ((long)(b * SQ + q0 + orow)) * DQ + h * HDQ + c0;
        *(uint4*)&ctxh[base]     = make_uint4(hv[0], hv[1], hv[2], hv[3]);
        *(uint4*)&ctxh[base + 8] = make_uint4(hv[4], hv[5], hv[6], hv[7]);
        *(uint4*)&ctxl[base]     = make_uint4(lv[0], lv[1], lv[2], lv[3]);
        *(uint4*)&ctxl[base + 8] = make_uint4(lv[4], lv[5], lv[6], lv[7]);
    }
}

// ---------------- host orchestration ----------------
extern "C" void kernel_launch(void* const* d_in, const int* in_sizes, int n_in,
                              void* d_out, int out_size) {
    const int*   x    = (const int*)  d_in[0];
    const float* tok  = (const float*)d_in[1];
    const float* pos  = (const float*)d_in[2];
    const float* ln1s = (const float*)d_in[3];
    const float* ln1b = (const float*)d_in[4];
    const float* wq   = (const float*)d_in[5];
    const float* wk   = (const float*)d_in[6];
    const float* wv   = (const float*)d_in[7];
    const float* wo   = (const float*)d_in[8];
    const float* bo   = (const float*)d_in[9];
    const float* ln2s = (const float*)d_in[10];
    const float* ln2b = (const float*)d_in[11];
    const float* w1   = (const float*)d_in[12];
    const float* b1   = (const float*)d_in[13];
    const float* w2   = (const float*)d_in[14];
    const float* b2   = (const float*)d_in[15];
    const float* fs   = (const float*)d_in[16];
    const float* fb   = (const float*)d_in[17];
    const float* wout = (const float*)d_in[18];
    float* out = (float*)d_out;

    float *h, *q, *k, *v;
    uint16_t *hnh, *hnl, *ctxh, *ctxl, *ffh, *ffl, *wth;
    cudaGetSymbolAddress((void**)&h,    g_h);
    cudaGetSymbolAddress((void**)&q,    g_q);
    cudaGetSymbolAddress((void**)&k,    g_k);
    cudaGetSymbolAddress((void**)&v,    g_v);
    cudaGetSymbolAddress((void**)&hnh,  g_hnh);
    cudaGetSymbolAddress((void**)&hnl,  g_hnl);
    cudaGetSymbolAddress((void**)&ctxh, g_ctxh);
    cudaGetSymbolAddress((void**)&ctxl, g_ctxl);
    cudaGetSymbolAddress((void**)&ffh,  g_ffh);
    cudaGetSymbolAddress((void**)&ffl,  g_ffl);
    cudaGetSymbolAddress((void**)&wth,  g_wth);

    const int GSMEM = 3 * STG;
    cudaFuncSetAttribute(gpt_flash, cudaFuncAttributeMaxDynamicSharedMemorySize, FLASH_SMEM);
    cudaFuncSetAttribute((const void*)gpt_bmma<2, false>, cudaFuncAttributeMaxDynamicSharedMemorySize, GSMEM);
    cudaFuncSetAttribute((const void*)gpt_bmma<3, false>, cudaFuncAttributeMaxDynamicSharedMemorySize, GSMEM);
    cudaFuncSetAttribute((const void*)gpt_bmma<0, true>,  cudaFuncAttributeMaxDynamicSharedMemorySize, GSMEM);
    cudaFuncSetAttribute((const void*)gpt_bmma_qkv,       cudaFuncAttributeMaxDynamicSharedMemorySize, GSMEM);

    dim3 wt(32, 8);
    gpt_wsplit<<<dim3(24, 24, 12), wt>>>(wq,  wth + WQ_OFF,  DQ, DQ, DQ,  (long)DQ*DQ,  (long)LSZ);
    gpt_wsplit<<<dim3(24, 24, 12), wt>>>(wk,  wth + WK_OFF,  DQ, DQ, DQ,  (long)DQ*DQ,  (long)LSZ);
    gpt_wsplit<<<dim3(24, 24, 12), wt>>>(wv,  wth + WV_OFF,  DQ, DQ, DQ,  (long)DQ*DQ,  (long)LSZ);
    gpt_wsplit<<<dim3(24, 24, 12), wt>>>(wo,  wth + WO_OFF,  DQ, DQ, DQ,  (long)DQ*DQ,  (long)LSZ);
    gpt_wsplit<<<dim3(96, 24, 12), wt>>>(w1,  wth + W1T_OFF, DQ, FFQ, FFQ, (long)DQ*FFQ, (long)LSZ);
    gpt_wsplit<<<dim3(24, 96, 12), wt>>>(w2,  wth + W2T_OFF, FFQ, DQ, DQ,  (long)FFQ*DQ, (long)LSZ);
    gpt_wsplit<<<dim3(VQP / 32, 24, 1), wt>>>(wout, wth + WOUT_OFF, DQ, VQ, VQP, 0, 0);

    gpt_embed<<<(NT * DQ + 255) / 256, 256>>>(x, tok, pos, h);

    dim3 gP (DQ / 128,  NT / 64);
    dim3 gQ (DQ / 128,  NT / 64, 3);
    dim3 gF1(FFQ / 128, NT / 64);
    dim3 gV (VQP / 128, 8);
    dim3 gFl(SQ / 64,   BQ * HQ);

    for (int l = 0; l < LQ; l++) {
        long lo = (long)l * LSZ;

        gpt_ln<<<NT, 256>>>(h, ln1s + l * DQ, ln1b + l * DQ, hnh, hnl);

        gpt_bmma_qkv<<<gQ, 256, GSMEM>>>(hnh, hnl, wth + lo + WQ_OFF, q, k, v);

        gpt_flash<<<gFl, 256, FLASH_SMEM>>>(q, k, v, ctxh, ctxl);

        gpt_bmma<2, false><<<gP, 256, GSMEM>>>(ctxh, ctxl,
            wth + lo + WO_OFF, bo + l * DQ, h, h, nullptr, nullptr, DQ, DQ, DQ, 1);

        gpt_ln<<<NT, 256>>>(h, ln2s + l * DQ, ln2b + l * DQ, hnh, hnl);

        gpt_bmma<3, false><<<gF1, 256, GSMEM>>>(hnh, hnl,
            wth + lo + W1T_OFF, b1 + l * FFQ, nullptr, nullptr, ffh, ffl, FFQ, DQ, FFQ, 1);

        gpt_bmma<2, false><<<gP, 256, GSMEM>>>(ffh, ffl,
            wth + lo + W2T_OFF, b2 + l * DQ, h, h, nullptr, nullptr, DQ, FFQ, DQ, 1);
    }

    gpt_ln<<<NT, 256>>>(h, fs, fb, hnh, hnl);

    gpt_bmma<0, true><<<gV, 256, GSMEM>>>(hnh, hnl,
        wth + WOUT_OFF, nullptr, nullptr, out, nullptr, nullptr, VQ, DQ, VQ, 4);
}

// round 14
// speedup vs baseline: 1.6650x; 1.1087x over previous
#include <cuda_runtime.h>
#include <cuda_fp16.h>
#include <math.h>
#include <stdint.h>

// ---------------- problem constants ----------------
#define BQ   4
#define SQ   512
#define DQ   768
#define HQ   12
#define HDQ  64
#define LQ   12
#define VQ   50257
#define VQP  50304
#define FFQ  3072
#define NT   (BQ*SQ)

#define WQ_OFF  0
#define WK_OFF  589824
#define WV_OFF  1179648
#define WO_OFF  1769472
#define W1T_OFF 2359296
#define W2T_OFF 4718592
#define LSZ     7077888
#define WOUT_OFF (12*LSZ)
#define WTOT     (WOUT_OFF + (long)VQP*DQ)

// ---------------- static scratch ----------------
__device__ __align__(128) float    g_h   [NT*DQ];
__device__ __align__(128) uint16_t g_qh  [NT*DQ],  g_ql  [NT*DQ];
__device__ __align__(128) uint16_t g_k16 [NT*DQ],  g_v16 [NT*DQ];
__device__ __align__(128) uint16_t g_hnh [NT*DQ],  g_hnl [NT*DQ];
__device__ __align__(128) uint16_t g_ctxh[NT*DQ],  g_ctxl[NT*DQ];
__device__ __align__(128) uint16_t g_ffh [NT*FFQ], g_ffl [NT*FFQ];
__device__ __align__(128) uint16_t g_wth [WTOT];   // fp16 W^T

// ---------------- helpers ----------------
__device__ __forceinline__ float gelu_f(float x) {
    const float c = 0.7978845608028654f;
    float x3 = x * x * x;
    return 0.5f * x * (1.0f + tanhf(c * (x + 0.044715f * x3)));
}

__device__ __forceinline__ uint32_t smem_u32(const void* p) {
    uint32_t a;
    asm("{ .reg .u64 t; cvta.to.shared.u64 t, %1; cvt.u32.u64 %0, t; }" : "=r"(a) : "l"(p));
    return a;
}

__device__ __forceinline__ void splith2(float a, float b, uint32_t& hi, uint32_t& lo) {
    __half ha = __float2half_rn(a), hb = __float2half_rn(b);
    float ra = a - __half2float(ha), rb = b - __half2float(hb);
    __half la = __float2half_rn(ra), lb = __float2half_rn(rb);
    hi = ((uint32_t)__half_as_ushort(hb) << 16) | (uint32_t)__half_as_ushort(ha);
    lo = ((uint32_t)__half_as_ushort(lb) << 16) | (uint32_t)__half_as_ushort(la);
}

__device__ __forceinline__ uint32_t packh2(float a, float b) {
    __half2 h = __float22half2_rn(make_float2(a, b));
    return *(uint32_t*)&h;
}

__device__ __forceinline__ void ldsm4(uint32_t& r0, uint32_t& r1, uint32_t& r2, uint32_t& r3,
                                      uint32_t addr) {
    asm volatile("ldmatrix.sync.aligned.m8n8.x4.shared.b16 {%0,%1,%2,%3}, [%4];"
        : "=r"(r0), "=r"(r1), "=r"(r2), "=r"(r3) : "r"(addr));
}

__device__ __forceinline__ void ldsm4t(uint32_t& r0, uint32_t& r1, uint32_t& r2, uint32_t& r3,
                                       uint32_t addr) {
    asm volatile("ldmatrix.sync.aligned.m8n8.x4.trans.shared.b16 {%0,%1,%2,%3}, [%4];"
        : "=r"(r0), "=r"(r1), "=r"(r2), "=r"(r3) : "r"(addr));
}

__device__ __forceinline__ void mma_f16(float* c, const uint32_t* a, const uint32_t* b) {
    asm volatile("mma.sync.aligned.m16n8k16.row.col.f32.f16.f16.f32 "
        "{%0,%1,%2,%3}, {%4,%5,%6,%7}, {%8,%9}, {%0,%1,%2,%3};"
        : "+f"(c[0]), "+f"(c[1]), "+f"(c[2]), "+f"(c[3])
        : "r"(a[0]), "r"(a[1]), "r"(a[2]), "r"(a[3]), "r"(b[0]), "r"(b[1]));
}

__device__ __forceinline__ void cpa16(uint32_t saddr, const void* g) {
    asm volatile("cp.async.cg.shared.global [%0], [%1], 16;" :: "r"(saddr), "l"(g));
}

// ---------------- weight transpose + fp16 convert ----------------
__global__ void gpt_wsplit(const float* __restrict__ W, uint16_t* __restrict__ Th,
                           int K, int N, int Npad, long ws, long ts) {
    int l = blockIdx.z;
    W  += (long)l * ws;
    Th += (long)l * ts;
    __shared__ float t[32][33];
    int n0 = blockIdx.x * 32, k0 = blockIdx.y * 32;
    int tx = threadIdx.x, ty = threadIdx.y;
    #pragma unroll
    for (int j = 0; j < 4; j++) {
        int n = n0 + tx;
        t[ty + j * 8][tx] = (n < N) ? W[(long)(k0 + ty + j * 8) * N + n] : 0.f;
    }
    __syncthreads();
    #pragma unroll
    for (int j = 0; j < 4; j++) {
        int n = n0 + ty + j * 8;
        if (n < Npad)
            Th[(long)n * K + k0 + tx] = __half_as_ushort(__float2half_rn(t[tx][ty + j * 8]));
    }
}

// ---------------- embedding ----------------
__global__ void gpt_embed(const int* __restrict__ x, const float* __restrict__ tok,
                          const float* __restrict__ pos, float* __restrict__ h) {
    int i = blockIdx.x * blockDim.x + threadIdx.x;
    if (i < NT * DQ) {
        int t = i / DQ, d = i - t * DQ;
        int s = t & (SQ - 1);
        h[i] = tok[(long)x[t] * DQ + d] + pos[s * DQ + d];
    }
}

// ---------------- layernorm: single pass, one sync ----------------
__global__ void gpt_ln(const float* __restrict__ in, const float* __restrict__ scale,
                       const float* __restrict__ shift,
                       uint16_t* __restrict__ oh, uint16_t* __restrict__ ol) {
    int t = blockIdx.x;
    const float* row = in + (long)t * DQ;
    int tid = threadIdx.x, lane = tid & 31, wid = tid >> 5;
    __shared__ float ws[8], wss[8];

    float x0 = row[tid], x1 = row[tid + 256], x2 = row[tid + 512];
    float s = x0 + x1 + x2;
    float ss = x0 * x0 + x1 * x1 + x2 * x2;
    #pragma unroll
    for (int o = 16; o > 0; o >>= 1) {
        s  += __shfl_xor_sync(0xffffffffu, s,  o);
        ss += __shfl_xor_sync(0xffffffffu, ss, o);
    }
    if (lane == 0) { ws[wid] = s; wss[wid] = ss; }
    __syncthreads();
    float S = 0.f, SS = 0.f;
    #pragma unroll
    for (int i = 0; i < 8; i++) { S += ws[i]; SS += wss[i]; }
    float mean = S * (1.0f / DQ);
    float inv = rsqrtf(SS * (1.0f / DQ) - mean * mean + 1e-5f);

    long base = (long)t * DQ;
    #pragma unroll
    for (int p = 0; p < 3; p++) {
        int d = tid + p * 256;
        float xv = (p == 0) ? x0 : (p == 1) ? x1 : x2;
        float v = scale[d] * (xv - mean) * inv + shift[d];
        __half hb = __float2half_rn(v);
        float r = v - __half2float(hb);
        oh[base + d] = __half_as_ushort(hb);
        ol[base + d] = __half_as_ushort(__float2half_rn(r));
    }
}

// ---------------- fp16x2 GEMM: K chunk 64, 3-stage cp.async, 2 CTAs/SM ----------------
// stage: Ah(64 rows) | Al(64) | B(128), rows of 144B (64 halves + pad). STG=36864.
#define BM   64
#define OAL  9216
#define OB   18432
#define STG  36864

__device__ __forceinline__ void load_stage(uint32_t sst,
    const uint16_t* __restrict__ Ah, const uint16_t* __restrict__ Al,
    const uint16_t* __restrict__ B,
    int bm, int bn, int K, int c, int tid) {
    #pragma unroll
    for (int p = 0; p < 4; p++) {
        int idx = tid + p * 256;
        int row = idx >> 3, seg = idx & 7;
        long go = (long)(bn + row) * K + c * 64 + seg * 8;
        cpa16(sst + OB + row * 144 + seg * 16, B + go);
    }
    #pragma unroll
    for (int p = 0; p < 2; p++) {
        int idx = tid + p * 256;
        int row = idx >> 3, seg = idx & 7;
        long go = (long)(bm + row) * K + c * 64 + seg * 8;
        uint32_t so = row * 144 + seg * 16;
        cpa16(sst + so,       Ah + go);
        cpa16(sst + OAL + so, Al + go);
    }
    asm volatile("cp.async.commit_group;" ::: "memory");
}

__device__ __forceinline__ void mma_stage(uint32_t sst, float acc[2][4][4],
        int wm, int wn, int a_row, int a_kof, int b_nof, int b_kof) {
    #pragma unroll
    for (int kk = 0; kk < 64; kk += 16) {
        uint32_t fah[2][4], fal[2][4], fb[4][2];
        #pragma unroll
        for (int ma = 0; ma < 2; ma++) {
            uint32_t ro = (uint32_t)((wm * 32 + ma * 16 + a_row) * 144 + (kk + a_kof) * 2);
            ldsm4(fah[ma][0], fah[ma][1], fah[ma][2], fah[ma][3], sst + ro);
        }
        #pragma unroll
        for (int np = 0; np < 2; np++) {
            uint32_t ro = (uint32_t)((wn * 32 + np * 16 + b_nof) * 144 + (kk + b_kof) * 2);
            ldsm4(fb[2*np][0], fb[2*np][1], fb[2*np+1][0], fb[2*np+1][1], sst + OB + ro);
        }
        #pragma unroll
        for (int ma = 0; ma < 2; ma++)
            #pragma unroll
            for (int na = 0; na < 4; na++)
                mma_f16(acc[ma][na], fah[ma], fb[na]);
        #pragma unroll
        for (int ma = 0; ma < 2; ma++) {
            uint32_t ro = (uint32_t)((wm * 32 + ma * 16 + a_row) * 144 + (kk + a_kof) * 2);
            ldsm4(fal[ma][0], fal[ma][1], fal[ma][2], fal[ma][3], sst + OAL + ro);
        }
        #pragma unroll
        for (int ma = 0; ma < 2; ma++)
            #pragma unroll
            for (int na = 0; na < 4; na++)
                mma_f16(acc[ma][na], fal[ma], fb[na]);
    }
}

// EPI: 0 fp32 plain; 2 fp32 +bias+res; 3 gelu(x+bias)->fp16 hi/lo;
//      4 fp16 hi/lo (no bias); 5 fp16 single (no bias). NG: guard gn.
template<int EPI, bool NG>
__device__ __forceinline__ void bmma_core(
    const uint16_t* __restrict__ Ah, const uint16_t* __restrict__ Al,
    const uint16_t* __restrict__ B,
    const float* __restrict__ bias, const float* __restrict__ res,
    float* __restrict__ C, uint16_t* __restrict__ Ch, uint16_t* __restrict__ Cl,
    int Ntot, int K, int ldc, int miter) {
    extern __shared__ __align__(16) char smem[];
    uint32_t sb = smem_u32(smem);
    int tid = threadIdx.x;
    int lane = tid & 31, wid = tid >> 5;
    int wm = wid >> 2, wn = wid & 3;
    int bn = blockIdx.x * 128;

    int l8 = lane & 7;
    int a_row = ((lane >> 3) & 1) * 8 + l8;
    int a_kof = (lane >> 4) * 8;
    int b_nof = (lane >> 4) * 8 + l8;
    int b_kof = ((lane >> 3) & 1) * 8;
    int g = lane >> 2, tig = lane & 3;
    const int NCH = K >> 6;

    for (int mi = 0; mi < miter; mi++) {
        int bm = (blockIdx.y * miter + mi) * BM;
        if (mi) __syncthreads();

        float acc[2][4][4];
        #pragma unroll
        for (int i = 0; i < 2; i++)
            #pragma unroll
            for (int j = 0; j < 4; j++)
                #pragma unroll
                for (int r2 = 0; r2 < 4; r2++) acc[i][j][r2] = 0.f;

        load_stage(sb,       Ah, Al, B, bm, bn, K, 0, tid);
        load_stage(sb + STG, Ah, Al, B, bm, bn, K, 1, tid);

        for (int c = 0; c < NCH; c++) {
            if (c + 1 < NCH) {
                asm volatile("cp.async.wait_group 1;" ::: "memory");
            } else {
                asm volatile("cp.async.wait_group 0;" ::: "memory");
            }
            __syncthreads();
            if (c + 2 < NCH)
                load_stage(sb + ((c + 2) % 3) * STG, Ah, Al, B, bm, bn, K, c + 2, tid);
            mma_stage(sb + (c % 3) * STG, acc, wm, wn, a_row, a_kof, b_nof, b_kof);
        }

        #pragma unroll
        for (int ma = 0; ma < 2; ma++) {
            int r0 = bm + wm * 32 + ma * 16 + g;
            #pragma unroll
            for (int na = 0; na < 4; na++) {
                int gn = bn + wn * 32 + na * 8 + 2 * tig;
                #pragma unroll
                for (int half = 0; half < 2; half++) {
                    int gm = r0 + half * 8;
                    float v0 = acc[ma][na][half * 2 + 0];
                    float v1 = acc[ma][na][half * 2 + 1];
                    long gi = (long)gm * ldc + gn;
                    if (NG) {
                        if (gn < Ntot)     C[gi]     = v0;
                        if (gn + 1 < Ntot) C[gi + 1] = v1;
                    } else if (EPI == 3) {
                        v0 = gelu_f(v0 + bias[gn]);
                        v1 = gelu_f(v1 + bias[gn + 1]);
                        uint32_t hh, ll;
                        splith2(v0, v1, hh, ll);
                        *(uint32_t*)&Ch[gi] = hh;
                        *(uint32_t*)&Cl[gi] = ll;
                    } else if (EPI == 4) {
                        uint32_t hh, ll;
                        splith2(v0, v1, hh, ll);
                        *(uint32_t*)&Ch[gi] = hh;
                        *(uint32_t*)&Cl[gi] = ll;
                    } else if (EPI == 5) {
                        *(uint32_t*)&Ch[gi] = packh2(v0, v1);
                    } else {
                        if (EPI == 2) {
                            v0 += bias[gn]     + res[gi];
                            v1 += bias[gn + 1] + res[gi + 1];
                        }
                        *(float2*)&C[gi] = make_float2(v0, v1);
                    }
                }
            }
        }
    }
}

template<int EPI, bool NG>
__global__ void __launch_bounds__(256, 2)
gpt_bmma(const uint16_t* __restrict__ Ah, const uint16_t* __restrict__ Al,
         const uint16_t* __restrict__ B,
         const float* __restrict__ bias, const float* __restrict__ res,
         float* __restrict__ C, uint16_t* __restrict__ Ch, uint16_t* __restrict__ Cl,
         int Ntot, int K, int ldc, int miter) {
    bmma_core<EPI, NG>(Ah, Al, B, bias, res, C, Ch, Cl, Ntot, K, ldc, miter);
}

// QKV: z=0 -> Q fp16 hi/lo, z=1 -> K fp16, z=2 -> V fp16
__global__ void __launch_bounds__(256, 2)
gpt_bmma_qkv(const uint16_t* __restrict__ Ah, const uint16_t* __restrict__ Al,
             const uint16_t* __restrict__ Wt,
             uint16_t* __restrict__ qh, uint16_t* __restrict__ ql,
             uint16_t* __restrict__ k16, uint16_t* __restrict__ v16) {
    int z = blockIdx.z;
    const uint16_t* B = Wt + (long)z * 589824;
    if (z == 0)
        bmma_core<4, false>(Ah, Al, B, nullptr, nullptr, nullptr, qh, ql, DQ, DQ, DQ, 1);
    else if (z == 1)
        bmma_core<5, false>(Ah, Al, B, nullptr, nullptr, nullptr, k16, nullptr, DQ, DQ, DQ, 1);
    else
        bmma_core<5, false>(Ah, Al, B, nullptr, nullptr, nullptr, v16, nullptr, DQ, DQ, DQ, 1);
}

// ---------------- tensor-core flash attention (fp16 inputs) ----------------
#define FSTR 72
#define FOQH 0
#define FOQL 9216
#define FOKS 18432
#define FOVS 27648
#define FOOS 36864           // Osum 64*66 floats
#define FOST 53760
#define FLASH_SMEM 55808

__global__ void __launch_bounds__(256, 2)
gpt_flash(const uint16_t* __restrict__ Qh, const uint16_t* __restrict__ Ql,
          const uint16_t* __restrict__ K16, const uint16_t* __restrict__ V16,
          uint16_t* __restrict__ ctxh, uint16_t* __restrict__ ctxl) {
    extern __shared__ __align__(16) char fsm[];
    uint32_t sb = smem_u32(fsm);
    float* Osum = (float*)(fsm + FOOS);
    float* rowm = (float*)(fsm + FOST);
    float* rowl = rowm + 64;
    float* rowf = rowm + 128;
    float* mnew = rowm + 192;
    float* pm   = rowm + 256;
    float* ps   = rowm + 384;

    int z = blockIdx.y;
    int b = z / HQ, h = z - b * HQ;
    int qt = blockIdx.x, q0 = qt * 64;
    int tid = threadIdx.x, lane = tid & 31, wid = tid >> 5;
    int wm = wid >> 1, wn = wid & 1;
    int r = tid & 63, dg = tid >> 6;

    int l8 = lane & 7;
    int a_row = ((lane >> 3) & 1) * 8 + l8;
    int a_kof = (lane >> 4) * 8;
    int b_nof = (lane >> 4) * 8 + l8;
    int b_kof = ((lane >> 3) & 1) * 8;
    int bt_row = ((lane >> 3) & 1) * 8 + l8;
    int bt_col = (lane >> 4) * 8;
    int g = lane >> 2, tig = lane & 3;
    int row0 = wm * 16 + g;

    // load Q tile (fp16 hi/lo): each thread copies its FULL 16-half slice (2x uint4)
    {
        long off = ((long)(b * SQ + q0 + r)) * DQ + h * HDQ + dg * 16;
        int so = r * 144 + dg * 32;
        *(uint4*)(fsm + FOQH + so)      = *(const uint4*)(Qh + off);
        *(uint4*)(fsm + FOQH + so + 16) = *(const uint4*)(Qh + off + 8);
        *(uint4*)(fsm + FOQL + so)      = *(const uint4*)(Ql + off);
        *(uint4*)(fsm + FOQL + so + 16) = *(const uint4*)(Ql + off + 8);
    }
    if (tid < 64) { rowm[tid] = -1e30f; rowl[tid] = 0.f; }

    float o[8][4];
    #pragma unroll
    for (int i = 0; i < 8; i++)
        #pragma unroll
        for (int j2 = 0; j2 < 4; j2++) o[i][j2] = 0.f;

    for (int j = 0; j <= qt; j++) {
        int k0 = j * 64;
        __syncthreads();
        {
            long off = ((long)(b * SQ + k0 + r)) * DQ + h * HDQ + dg * 16;
            int so = r * 144 + dg * 32;
            *(uint4*)(fsm + FOKS + so)      = *(const uint4*)(K16 + off);
            *(uint4*)(fsm + FOKS + so + 16) = *(const uint4*)(K16 + off + 8);
            *(uint4*)(fsm + FOVS + so)      = *(const uint4*)(V16 + off);
            *(uint4*)(fsm + FOVS + so + 16) = *(const uint4*)(V16 + off + 8);
        }
        __syncthreads();

        // S = Q K^T
        float s[4][4];
        #pragma unroll
        for (int na = 0; na < 4; na++)
            #pragma unroll
            for (int v2 = 0; v2 < 4; v2++) s[na][v2] = 0.f;
        #pragma unroll
        for (int kk = 0; kk < 64; kk += 16) {
            uint32_t fah[4], fal[4], fb[4][2];
            uint32_t aro = (uint32_t)((wm * 16 + a_row) * FSTR + kk + a_kof) * 2;
            ldsm4(fah[0], fah[1], fah[2], fah[3], sb + FOQH + aro);
            ldsm4(fal[0], fal[1], fal[2], fal[3], sb + FOQL + aro);
            #pragma unroll
            for (int np = 0; np < 2; np++) {
                uint32_t ro = (uint32_t)((wn * 32 + np * 16 + b_nof) * FSTR + kk + b_kof) * 2;
                ldsm4(fb[2*np][0], fb[2*np][1], fb[2*np+1][0], fb[2*np+1][1], sb + FOKS + ro);
            }
            #pragma unroll
            for (int na = 0; na < 4; na++) mma_f16(s[na], fah, fb[na]);
            #pragma unroll
            for (int na = 0; na < 4; na++) mma_f16(s[na], fal, fb[na]);
        }
        #pragma unroll
        for (int na = 0; na < 4; na++)
            #pragma unroll
            for (int v2 = 0; v2 < 4; v2++) {
                s[na][v2] *= 0.125f;
                if (j == qt) {
                    int kc = wn * 32 + na * 8 + 2 * tig + (v2 & 1);
                    int qr = row0 + (v2 >> 1) * 8;
                    if (kc > qr) s[na][v2] = -1e30f;
                }
            }
        {
            float m0 = -1e30f, m1 = -1e30f;
            #pragma unroll
            for (int na = 0; na < 4; na++) {
                m0 = fmaxf(m0, fmaxf(s[na][0], s[na][1]));
                m1 = fmaxf(m1, fmaxf(s[na][2], s[na][3]));
            }
            m0 = fmaxf(m0, __shfl_xor_sync(0xffffffffu, m0, 1));
            m0 = fmaxf(m0, __shfl_xor_sync(0xffffffffu, m0, 2));
            m1 = fmaxf(m1, __shfl_xor_sync(0xffffffffu, m1, 1));
            m1 = fmaxf(m1, __shfl_xor_sync(0xffffffffu, m1, 2));
            if (tig == 0) { pm[wn * 64 + row0] = m0; pm[wn * 64 + row0 + 8] = m1; }
        }
        __syncthreads();
        if (tid < 64) {
            float mo = rowm[tid];
            float mn = fmaxf(mo, fmaxf(pm[tid], pm[64 + tid]));
            mnew[tid] = mn;
            rowf[tid] = __expf(mo - mn);
            rowm[tid] = mn;
        }
        __syncthreads();

        uint32_t ah[2][4], al[2][4];
        {
            float mn0 = mnew[row0], mn1 = mnew[row0 + 8];
            float sum0 = 0.f, sum1 = 0.f;
            #pragma unroll
            for (int na = 0; na < 4; na++) {
                float p0 = __expf(s[na][0] - mn0);
                float p1 = __expf(s[na][1] - mn0);
                float p2 = __expf(s[na][2] - mn1);
                float p3 = __expf(s[na][3] - mn1);
                sum0 += p0 + p1; sum1 += p2 + p3;
                uint32_t h01, l01, h23, l23;
                splith2(p0, p1, h01, l01);
                splith2(p2, p3, h23, l23);
                int j2 = na >> 1;
                if ((na & 1) == 0) {
                    ah[j2][0] = h01; ah[j2][1] = h23;
                    al[j2][0] = l01; al[j2][1] = l23;
                } else {
                    ah[j2][2] = h01; ah[j2][3] = h23;
                    al[j2][2] = l01; al[j2][3] = l23;
                }
            }
            sum0 += __shfl_xor_sync(0xffffffffu, sum0, 1);
            sum0 += __shfl_xor_sync(0xffffffffu, sum0, 2);
            sum1 += __shfl_xor_sync(0xffffffffu, sum1, 1);
            sum1 += __shfl_xor_sync(0xffffffffu, sum1, 2);
            if (tig == 0) { ps[wn * 64 + row0] = sum0; ps[wn * 64 + row0 + 8] = sum1; }
        }
        __syncthreads();
        if (tid < 64) rowl[tid] = rowl[tid] * rowf[tid] + ps[tid] + ps[64 + tid];

        {
            float f0 = rowf[row0], f1 = rowf[row0 + 8];
            #pragma unroll
            for (int nd = 0; nd < 8; nd++) {
                o[nd][0] *= f0; o[nd][1] *= f0;
                o[nd][2] *= f1; o[nd][3] *= f1;
            }
        }
        #pragma unroll
        for (int jj = 0; jj < 2; jj++) {
            uint32_t fbv[8][2];
            #pragma unroll
            for (int nb = 0; nb < 4; nb++) {
                uint32_t ro = (uint32_t)((wn * 32 + jj * 16 + bt_row) * FSTR + nb * 16 + bt_col) * 2;
                ldsm4t(fbv[2*nb][0], fbv[2*nb][1], fbv[2*nb+1][0], fbv[2*nb+1][1],
                       sb + FOVS + ro);
            }
            #pragma unroll
            for (int nd = 0; nd < 8; nd++) mma_f16(o[nd], ah[jj], fbv[nd]);
            #pragma unroll
            for (int nd = 0; nd < 8; nd++) mma_f16(o[nd], al[jj], fbv[nd]);
        }
    }

    __syncthreads();
    if (wn == 0) {
        #pragma unroll
        for (int nd = 0; nd < 8; nd++)
            #pragma unroll
            for (int v2 = 0; v2 < 4; v2++)
                Osum[(row0 + (v2 >> 1) * 8) * 66 + nd * 8 + 2 * tig + (v2 & 1)] = o[nd][v2];
    }
    __syncthreads();
    if (wn == 1) {
        #pragma unroll
        for (int nd = 0; nd < 8; nd++)
            #pragma unroll
            for (int v2 = 0; v2 < 4; v2++)
                Osum[(row0 + (v2 >> 1) * 8) * 66 + nd * 8 + 2 * tig + (v2 & 1)] += o[nd][v2];
    }
    __syncthreads();
    {
        int orow = tid >> 2, c0 = (tid & 3) * 16;
        float inv = 1.0f / rowl[orow];
        uint32_t hv[8], lv[8];
        #pragma unroll
        for (int i = 0; i < 8; i++) {
            float v0 = Osum[orow * 66 + c0 + 2 * i]     * inv;
            float v1 = Osum[orow * 66 + c0 + 2 * i + 1] * inv;
            splith2(v0, v1, hv[i], lv[i]);
        }
        long base = ((long)(b * SQ + q0 + orow)) * DQ + h * HDQ + c0;
        *(uint4*)&ctxh[base]     = make_uint4(hv[0], hv[1], hv[2], hv[3]);
        *(uint4*)&ctxh[base + 8] = make_uint4(hv[4], hv[5], hv[6], hv[7]);
        *(uint4*)&ctxl[base]     = make_uint4(lv[0], lv[1], lv[2], lv[3]);
        *(uint4*)&ctxl[base + 8] = make_uint4(lv[4], lv[5], lv[6], lv[7]);
    }
}

// ---------------- host orchestration ----------------
extern "C" void kernel_launch(void* const* d_in, const int* in_sizes, int n_in,
                              void* d_out, int out_size) {
    const int*   x    = (const int*)  d_in[0];
    const float* tok  = (const float*)d_in[1];
    const float* pos  = (const float*)d_in[2];
    const float* ln1s = (const float*)d_in[3];
    const float* ln1b = (const float*)d_in[4];
    const float* wq   = (const float*)d_in[5];
    const float* wk   = (const float*)d_in[6];
    const float* wv   = (const float*)d_in[7];
    const float* wo   = (const float*)d_in[8];
    const float* bo   = (const float*)d_in[9];
    const float* ln2s = (const float*)d_in[10];
    const float* ln2b = (const float*)d_in[11];
    const float* w1   = (const float*)d_in[12];
    const float* b1   = (const float*)d_in[13];
    const float* w2   = (const float*)d_in[14];
    const float* b2   = (const float*)d_in[15];
    const float* fs   = (const float*)d_in[16];
    const float* fb   = (const float*)d_in[17];
    const float* wout = (const float*)d_in[18];
    float* out = (float*)d_out;

    float* h;
    uint16_t *qh, *ql, *k16, *v16;
    uint16_t *hnh, *hnl, *ctxh, *ctxl, *ffh, *ffl, *wth;
    cudaGetSymbolAddress((void**)&h,    g_h);
    cudaGetSymbolAddress((void**)&qh,   g_qh);
    cudaGetSymbolAddress((void**)&ql,   g_ql);
    cudaGetSymbolAddress((void**)&k16,  g_k16);
    cudaGetSymbolAddress((void**)&v16,  g_v16);
    cudaGetSymbolAddress((void**)&hnh,  g_hnh);
    cudaGetSymbolAddress((void**)&hnl,  g_hnl);
    cudaGetSymbolAddress((void**)&ctxh, g_ctxh);
    cudaGetSymbolAddress((void**)&ctxl, g_ctxl);
    cudaGetSymbolAddress((void**)&ffh,  g_ffh);
    cudaGetSymbolAddress((void**)&ffl,  g_ffl);
    cudaGetSymbolAddress((void**)&wth,  g_wth);

    const int GSMEM = 3 * STG;   // 110592
    cudaFuncSetAttribute(gpt_flash, cudaFuncAttributeMaxDynamicSharedMemorySize, FLASH_SMEM);
    cudaFuncSetAttribute((const void*)gpt_bmma<2, false>, cudaFuncAttributeMaxDynamicSharedMemorySize, GSMEM);
    cudaFuncSetAttribute((const void*)gpt_bmma<3, false>, cudaFuncAttributeMaxDynamicSharedMemorySize, GSMEM);
    cudaFuncSetAttribute((const void*)gpt_bmma<0, true>,  cudaFuncAttributeMaxDynamicSharedMemorySize, GSMEM);
    cudaFuncSetAttribute((const void*)gpt_bmma_qkv,       cudaFuncAttributeMaxDynamicSharedMemorySize, GSMEM);

    dim3 wt(32, 8);
    gpt_wsplit<<<dim3(24, 24, 12), wt>>>(wq,  wth + WQ_OFF,  DQ, DQ, DQ,  (long)DQ*DQ,  (long)LSZ);
    gpt_wsplit<<<dim3(24, 24, 12), wt>>>(wk,  wth + WK_OFF,  DQ, DQ, DQ,  (long)DQ*DQ,  (long)LSZ);
    gpt_wsplit<<<dim3(24, 24, 12), wt>>>(wv,  wth + WV_OFF,  DQ, DQ, DQ,  (long)DQ*DQ,  (long)LSZ);
    gpt_wsplit<<<dim3(24, 24, 12), wt>>>(wo,  wth + WO_OFF,  DQ, DQ, DQ,  (long)DQ*DQ,  (long)LSZ);
    gpt_wsplit<<<dim3(96, 24, 12), wt>>>(w1,  wth + W1T_OFF, DQ, FFQ, FFQ, (long)DQ*FFQ, (long)LSZ);
    gpt_wsplit<<<dim3(24, 96, 12), wt>>>(w2,  wth + W2T_OFF, FFQ, DQ, DQ,  (long)FFQ*DQ, (long)LSZ);
    gpt_wsplit<<<dim3(VQP / 32, 24, 1), wt>>>(wout, wth + WOUT_OFF, DQ, VQ, VQP, 0, 0);

    gpt_embed<<<(NT * DQ + 255) / 256, 256>>>(x, tok, pos, h);

    dim3 gP (DQ / 128,  NT / 64);
    dim3 gQ (DQ / 128,  NT / 64, 3);
    dim3 gF1(FFQ / 128, NT / 64);
    dim3 gV (VQP / 128, 8);
    dim3 gFl(SQ / 64,   BQ * HQ);

    for (int l = 0; l < LQ; l++) {
        long lo = (long)l * LSZ;

        gpt_ln<<<NT, 256>>>(h, ln1s + l * DQ, ln1b + l * DQ, hnh, hnl);

        gpt_bmma_qkv<<<gQ, 256, GSMEM>>>(hnh, hnl, wth + lo + WQ_OFF, qh, ql, k16, v16);

        gpt_flash<<<gFl, 256, FLASH_SMEM>>>(qh, ql, k16, v16, ctxh, ctxl);

        gpt_bmma<2, false><<<gP, 256, GSMEM>>>(ctxh, ctxl,
            wth + lo + WO_OFF, bo + l * DQ, h, h, nullptr, nullptr, DQ, DQ, DQ, 1);

        gpt_ln<<<NT, 256>>>(h, ln2s + l * DQ, ln2b + l * DQ, hnh, hnl);

        gpt_bmma<3, false><<<gF1, 256, GSMEM>>>(hnh, hnl,
            wth + lo + W1T_OFF, b1 + l * FFQ, nullptr, nullptr, ffh, ffl, FFQ, DQ, FFQ, 1);

        gpt_bmma<2, false><<<gP, 256, GSMEM>>>(ffh, ffl,
            wth + lo + W2T_OFF, b2 + l * DQ, h, h, nullptr, nullptr, DQ, FFQ, DQ, 1);
    }

    gpt_ln<<<NT, 256>>>(h, fs, fb, hnh, hnl);

    gpt_bmma<0, true><<<gV, 256, GSMEM>>>(hnh, hnl,
        wth + WOUT_OFF, nullptr, nullptr, out, nullptr, nullptr, VQ, DQ, VQ, 4);
}

// round 15
// speedup vs baseline: 1.8164x; 1.0909x over previous
#include <cuda_runtime.h>
#include <cuda_fp16.h>
#include <math.h>
#include <stdint.h>

// ---------------- problem constants ----------------
#define BQ   4
#define SQ   512
#define DQ   768
#define HQ   12
#define HDQ  64
#define LQ   12
#define VQ   50257
#define VQP  50304
#define FFQ  3072
#define NT   (BQ*SQ)

#define WQ_OFF  0
#define WK_OFF  589824
#define WV_OFF  1179648
#define WO_OFF  1769472
#define W1T_OFF 2359296
#define W2T_OFF 4718592
#define LSZ     7077888
#define WOUT_OFF (12*LSZ)
#define WTOT     (WOUT_OFF + (long)VQP*DQ)

// ---------------- static scratch ----------------
__device__ __align__(128) float    g_h   [NT*DQ];
__device__ __align__(128) uint16_t g_qh  [NT*DQ],  g_ql  [NT*DQ];
__device__ __align__(128) uint16_t g_k16 [NT*DQ],  g_v16 [NT*DQ];
__device__ __align__(128) uint16_t g_hnh [NT*DQ],  g_hnl [NT*DQ];
__device__ __align__(128) uint16_t g_ctxh[NT*DQ],  g_ctxl[NT*DQ];
__device__ __align__(128) uint16_t g_ffh [NT*FFQ], g_ffl [NT*FFQ];
__device__ __align__(128) uint16_t g_wth [WTOT];   // fp16 W^T

// ---------------- helpers ----------------
__device__ __forceinline__ float gelu_f(float x) {
    const float c = 0.7978845608028654f;
    float x3 = x * x * x;
    return 0.5f * x * (1.0f + tanhf(c * (x + 0.044715f * x3)));
}

__device__ __forceinline__ uint32_t smem_u32(const void* p) {
    uint32_t a;
    asm("{ .reg .u64 t; cvta.to.shared.u64 t, %1; cvt.u32.u64 %0, t; }" : "=r"(a) : "l"(p));
    return a;
}

__device__ __forceinline__ void splith2(float a, float b, uint32_t& hi, uint32_t& lo) {
    __half ha = __float2half_rn(a), hb = __float2half_rn(b);
    float ra = a - __half2float(ha), rb = b - __half2float(hb);
    __half la = __float2half_rn(ra), lb = __float2half_rn(rb);
    hi = ((uint32_t)__half_as_ushort(hb) << 16) | (uint32_t)__half_as_ushort(ha);
    lo = ((uint32_t)__half_as_ushort(lb) << 16) | (uint32_t)__half_as_ushort(la);
}

__device__ __forceinline__ uint32_t packh2(float a, float b) {
    __half2 h = __float22half2_rn(make_float2(a, b));
    return *(uint32_t*)&h;
}

__device__ __forceinline__ void ldsm4(uint32_t& r0, uint32_t& r1, uint32_t& r2, uint32_t& r3,
                                      uint32_t addr) {
    asm volatile("ldmatrix.sync.aligned.m8n8.x4.shared.b16 {%0,%1,%2,%3}, [%4];"
        : "=r"(r0), "=r"(r1), "=r"(r2), "=r"(r3) : "r"(addr));
}

__device__ __forceinline__ void ldsm4t(uint32_t& r0, uint32_t& r1, uint32_t& r2, uint32_t& r3,
                                       uint32_t addr) {
    asm volatile("ldmatrix.sync.aligned.m8n8.x4.trans.shared.b16 {%0,%1,%2,%3}, [%4];"
        : "=r"(r0), "=r"(r1), "=r"(r2), "=r"(r3) : "r"(addr));
}

__device__ __forceinline__ void mma_f16(float* c, const uint32_t* a, const uint32_t* b) {
    asm volatile("mma.sync.aligned.m16n8k16.row.col.f32.f16.f16.f32 "
        "{%0,%1,%2,%3}, {%4,%5,%6,%7}, {%8,%9}, {%0,%1,%2,%3};"
        : "+f"(c[0]), "+f"(c[1]), "+f"(c[2]), "+f"(c[3])
        : "r"(a[0]), "r"(a[1]), "r"(a[2]), "r"(a[3]), "r"(b[0]), "r"(b[1]));
}

__device__ __forceinline__ void cpa16(uint32_t saddr, const void* g) {
    asm volatile("cp.async.cg.shared.global [%0], [%1], 16;" :: "r"(saddr), "l"(g));
}

// ---------------- weight transpose + fp16 convert ----------------
__global__ void gpt_wsplit(const float* __restrict__ W, uint16_t* __restrict__ Th,
                           int K, int N, int Npad, long ws, long ts) {
    int l = blockIdx.z;
    W  += (long)l * ws;
    Th += (long)l * ts;
    __shared__ float t[32][33];
    int n0 = blockIdx.x * 32, k0 = blockIdx.y * 32;
    int tx = threadIdx.x, ty = threadIdx.y;
    #pragma unroll
    for (int j = 0; j < 4; j++) {
        int n = n0 + tx;
        t[ty + j * 8][tx] = (n < N) ? W[(long)(k0 + ty + j * 8) * N + n] : 0.f;
    }
    __syncthreads();
    #pragma unroll
    for (int j = 0; j < 4; j++) {
        int n = n0 + ty + j * 8;
        if (n < Npad)
            Th[(long)n * K + k0 + tx] = __half_as_ushort(__float2half_rn(t[tx][ty + j * 8]));
    }
}

// ---------------- embedding ----------------
__global__ void gpt_embed(const int* __restrict__ x, const float* __restrict__ tok,
                          const float* __restrict__ pos, float* __restrict__ h) {
    int i = blockIdx.x * blockDim.x + threadIdx.x;
    if (i < NT * DQ) {
        int t = i / DQ, d = i - t * DQ;
        int s = t & (SQ - 1);
        h[i] = tok[(long)x[t] * DQ + d] + pos[s * DQ + d];
    }
}

// ---------------- layernorm: single pass, one sync ----------------
__global__ void gpt_ln(const float* __restrict__ in, const float* __restrict__ scale,
                       const float* __restrict__ shift,
                       uint16_t* __restrict__ oh, uint16_t* __restrict__ ol) {
    int t = blockIdx.x;
    const float* row = in + (long)t * DQ;
    int tid = threadIdx.x, lane = tid & 31, wid = tid >> 5;
    __shared__ float ws[8], wss[8];

    float x0 = row[tid], x1 = row[tid + 256], x2 = row[tid + 512];
    float s = x0 + x1 + x2;
    float ss = x0 * x0 + x1 * x1 + x2 * x2;
    #pragma unroll
    for (int o = 16; o > 0; o >>= 1) {
        s  += __shfl_xor_sync(0xffffffffu, s,  o);
        ss += __shfl_xor_sync(0xffffffffu, ss, o);
    }
    if (lane == 0) { ws[wid] = s; wss[wid] = ss; }
    __syncthreads();
    float S = 0.f, SS = 0.f;
    #pragma unroll
    for (int i = 0; i < 8; i++) { S += ws[i]; SS += wss[i]; }
    float mean = S * (1.0f / DQ);
    float inv = rsqrtf(SS * (1.0f / DQ) - mean * mean + 1e-5f);

    long base = (long)t * DQ;
    #pragma unroll
    for (int p = 0; p < 3; p++) {
        int d = tid + p * 256;
        float xv = (p == 0) ? x0 : (p == 1) ? x1 : x2;
        float v = scale[d] * (xv - mean) * inv + shift[d];
        __half hb = __float2half_rn(v);
        float r = v - __half2float(hb);
        oh[base + d] = __half_as_ushort(hb);
        ol[base + d] = __half_as_ushort(__float2half_rn(r));
    }
}

// ---------------- fp16 GEMM: K chunk 64, 3-stage cp.async, 2 CTAs/SM ----------------
// LO: also use the activation-lo chain (dual-chain). Single-chain skips Al entirely.
// stage: Ah(64 rows) | Al(64) | B(128), rows of 144B. STG=36864.
#define BM   64
#define OAL  9216
#define OB   18432
#define STG  36864

template<bool LO>
__device__ __forceinline__ void load_stage(uint32_t sst,
    const uint16_t* __restrict__ Ah, const uint16_t* __restrict__ Al,
    const uint16_t* __restrict__ B,
    int bm, int bn, int K, int c, int tid) {
    #pragma unroll
    for (int p = 0; p < 4; p++) {
        int idx = tid + p * 256;
        int row = idx >> 3, seg = idx & 7;
        long go = (long)(bn + row) * K + c * 64 + seg * 8;
        cpa16(sst + OB + row * 144 + seg * 16, B + go);
    }
    #pragma unroll
    for (int p = 0; p < 2; p++) {
        int idx = tid + p * 256;
        int row = idx >> 3, seg = idx & 7;
        long go = (long)(bm + row) * K + c * 64 + seg * 8;
        uint32_t so = row * 144 + seg * 16;
        cpa16(sst + so, Ah + go);
        if (LO) cpa16(sst + OAL + so, Al + go);
    }
    asm volatile("cp.async.commit_group;" ::: "memory");
}

template<bool LO>
__device__ __forceinline__ void mma_stage(uint32_t sst, float acc[2][4][4],
        int wm, int wn, int a_row, int a_kof, int b_nof, int b_kof) {
    #pragma unroll
    for (int kk = 0; kk < 64; kk += 16) {
        uint32_t fah[2][4], fb[4][2];
        #pragma unroll
        for (int ma = 0; ma < 2; ma++) {
            uint32_t ro = (uint32_t)((wm * 32 + ma * 16 + a_row) * 144 + (kk + a_kof) * 2);
            ldsm4(fah[ma][0], fah[ma][1], fah[ma][2], fah[ma][3], sst + ro);
        }
        #pragma unroll
        for (int np = 0; np < 2; np++) {
            uint32_t ro = (uint32_t)((wn * 32 + np * 16 + b_nof) * 144 + (kk + b_kof) * 2);
            ldsm4(fb[2*np][0], fb[2*np][1], fb[2*np+1][0], fb[2*np+1][1], sst + OB + ro);
        }
        #pragma unroll
        for (int ma = 0; ma < 2; ma++)
            #pragma unroll
            for (int na = 0; na < 4; na++)
                mma_f16(acc[ma][na], fah[ma], fb[na]);
        if (LO) {
            uint32_t fal[2][4];
            #pragma unroll
            for (int ma = 0; ma < 2; ma++) {
                uint32_t ro = (uint32_t)((wm * 32 + ma * 16 + a_row) * 144 + (kk + a_kof) * 2);
                ldsm4(fal[ma][0], fal[ma][1], fal[ma][2], fal[ma][3], sst + OAL + ro);
            }
            #pragma unroll
            for (int ma = 0; ma < 2; ma++)
                #pragma unroll
                for (int na = 0; na < 4; na++)
                    mma_f16(acc[ma][na], fal[ma], fb[na]);
        }
    }
}

// EPI: 0 fp32 plain; 2 fp32 +bias+res; 3 gelu(x+bias)->fp16 hi/lo;
//      4 fp16 hi/lo (no bias); 5 fp16 single (no bias). NG: guard gn.
template<int EPI, bool NG, bool LO>
__device__ __forceinline__ void bmma_core(
    const uint16_t* __restrict__ Ah, const uint16_t* __restrict__ Al,
    const uint16_t* __restrict__ B,
    const float* __restrict__ bias, const float* __restrict__ res,
    float* __restrict__ C, uint16_t* __restrict__ Ch, uint16_t* __restrict__ Cl,
    int Ntot, int K, int ldc, int miter) {
    extern __shared__ __align__(16) char smem[];
    uint32_t sb = smem_u32(smem);
    int tid = threadIdx.x;
    int lane = tid & 31, wid = tid >> 5;
    int wm = wid >> 2, wn = wid & 3;
    int bn = blockIdx.x * 128;

    int l8 = lane & 7;
    int a_row = ((lane >> 3) & 1) * 8 + l8;
    int a_kof = (lane >> 4) * 8;
    int b_nof = (lane >> 4) * 8 + l8;
    int b_kof = ((lane >> 3) & 1) * 8;
    int g = lane >> 2, tig = lane & 3;
    const int NCH = K >> 6;

    for (int mi = 0; mi < miter; mi++) {
        int bm = (blockIdx.y * miter + mi) * BM;
        if (mi) __syncthreads();

        float acc[2][4][4];
        #pragma unroll
        for (int i = 0; i < 2; i++)
            #pragma unroll
            for (int j = 0; j < 4; j++)
                #pragma unroll
                for (int r2 = 0; r2 < 4; r2++) acc[i][j][r2] = 0.f;

        load_stage<LO>(sb,       Ah, Al, B, bm, bn, K, 0, tid);
        load_stage<LO>(sb + STG, Ah, Al, B, bm, bn, K, 1, tid);

        for (int c = 0; c < NCH; c++) {
            if (c + 1 < NCH) {
                asm volatile("cp.async.wait_group 1;" ::: "memory");
            } else {
                asm volatile("cp.async.wait_group 0;" ::: "memory");
            }
            __syncthreads();
            if (c + 2 < NCH)
                load_stage<LO>(sb + ((c + 2) % 3) * STG, Ah, Al, B, bm, bn, K, c + 2, tid);
            mma_stage<LO>(sb + (c % 3) * STG, acc, wm, wn, a_row, a_kof, b_nof, b_kof);
        }

        #pragma unroll
        for (int ma = 0; ma < 2; ma++) {
            int r0 = bm + wm * 32 + ma * 16 + g;
            #pragma unroll
            for (int na = 0; na < 4; na++) {
                int gn = bn + wn * 32 + na * 8 + 2 * tig;
                #pragma unroll
                for (int half = 0; half < 2; half++) {
                    int gm = r0 + half * 8;
                    float v0 = acc[ma][na][half * 2 + 0];
                    float v1 = acc[ma][na][half * 2 + 1];
                    long gi = (long)gm * ldc + gn;
                    if (NG) {
                        if (gn < Ntot)     C[gi]     = v0;
                        if (gn + 1 < Ntot) C[gi + 1] = v1;
                    } else if (EPI == 3) {
                        v0 = gelu_f(v0 + bias[gn]);
                        v1 = gelu_f(v1 + bias[gn + 1]);
                        uint32_t hh, ll;
                        splith2(v0, v1, hh, ll);
                        *(uint32_t*)&Ch[gi] = hh;
                        *(uint32_t*)&Cl[gi] = ll;
                    } else if (EPI == 4) {
                        uint32_t hh, ll;
                        splith2(v0, v1, hh, ll);
                        *(uint32_t*)&Ch[gi] = hh;
                        *(uint32_t*)&Cl[gi] = ll;
                    } else if (EPI == 5) {
                        *(uint32_t*)&Ch[gi] = packh2(v0, v1);
                    } else {
                        if (EPI == 2) {
                            v0 += bias[gn]     + res[gi];
                            v1 += bias[gn + 1] + res[gi + 1];
                        }
                        *(float2*)&C[gi] = make_float2(v0, v1);
                    }
                }
            }
        }
    }
}

template<int EPI, bool NG, bool LO>
__global__ void __launch_bounds__(256, 2)
gpt_bmma(const uint16_t* __restrict__ Ah, const uint16_t* __restrict__ Al,
         const uint16_t* __restrict__ B,
         const float* __restrict__ bias, const float* __restrict__ res,
         float* __restrict__ C, uint16_t* __restrict__ Ch, uint16_t* __restrict__ Cl,
         int Ntot, int K, int ldc, int miter) {
    bmma_core<EPI, NG, LO>(Ah, Al, B, bias, res, C, Ch, Cl, Ntot, K, ldc, miter);
}

// QKV: z=0 -> Q fp16 hi/lo (dual chain), z=1 -> K fp16 (single), z=2 -> V fp16 (single)
__global__ void __launch_bounds__(256, 2)
gpt_bmma_qkv(const uint16_t* __restrict__ Ah, const uint16_t* __restrict__ Al,
             const uint16_t* __restrict__ Wt,
             uint16_t* __restrict__ qh, uint16_t* __restrict__ ql,
             uint16_t* __restrict__ k16, uint16_t* __restrict__ v16) {
    int z = blockIdx.z;
    const uint16_t* B = Wt + (long)z * 589824;
    if (z == 0)
        bmma_core<4, false, true>(Ah, Al, B, nullptr, nullptr, nullptr, qh, ql, DQ, DQ, DQ, 1);
    else if (z == 1)
        bmma_core<5, false, false>(Ah, Al, B, nullptr, nullptr, nullptr, k16, nullptr, DQ, DQ, DQ, 1);
    else
        bmma_core<5, false, false>(Ah, Al, B, nullptr, nullptr, nullptr, v16, nullptr, DQ, DQ, DQ, 1);
}

// ---------------- tensor-core flash attention (fp16 inputs) ----------------
#define FSTR 72
#define FOQH 0
#define FOQL 9216
#define FOKS 18432
#define FOVS 27648
#define FOOS 36864           // Osum 64*66 floats
#define FOST 53760
#define FLASH_SMEM 55808

__global__ void __launch_bounds__(256, 2)
gpt_flash(const uint16_t* __restrict__ Qh, const uint16_t* __restrict__ Ql,
          const uint16_t* __restrict__ K16, const uint16_t* __restrict__ V16,
          uint16_t* __restrict__ ctxh, uint16_t* __restrict__ ctxl) {
    extern __shared__ __align__(16) char fsm[];
    uint32_t sb = smem_u32(fsm);
    float* Osum = (float*)(fsm + FOOS);
    float* rowm = (float*)(fsm + FOST);
    float* rowl = rowm + 64;
    float* rowf = rowm + 128;
    float* mnew = rowm + 192;
    float* pm   = rowm + 256;
    float* ps   = rowm + 384;

    int z = blockIdx.y;
    int b = z / HQ, h = z - b * HQ;
    int qt = blockIdx.x, q0 = qt * 64;
    int tid = threadIdx.x, lane = tid & 31, wid = tid >> 5;
    int wm = wid >> 1, wn = wid & 1;
    int r = tid & 63, dg = tid >> 6;

    int l8 = lane & 7;
    int a_row = ((lane >> 3) & 1) * 8 + l8;
    int a_kof = (lane >> 4) * 8;
    int b_nof = (lane >> 4) * 8 + l8;
    int b_kof = ((lane >> 3) & 1) * 8;
    int bt_row = ((lane >> 3) & 1) * 8 + l8;
    int bt_col = (lane >> 4) * 8;
    int g = lane >> 2, tig = lane & 3;
    int row0 = wm * 16 + g;

    // load Q tile (fp16 hi/lo): full 16-half slice per thread (2x uint4)
    {
        long off = ((long)(b * SQ + q0 + r)) * DQ + h * HDQ + dg * 16;
        int so = r * 144 + dg * 32;
        *(uint4*)(fsm + FOQH + so)      = *(const uint4*)(Qh + off);
        *(uint4*)(fsm + FOQH + so + 16) = *(const uint4*)(Qh + off + 8);
        *(uint4*)(fsm + FOQL + so)      = *(const uint4*)(Ql + off);
        *(uint4*)(fsm + FOQL + so + 16) = *(const uint4*)(Ql + off + 8);
    }
    if (tid < 64) { rowm[tid] = -1e30f; rowl[tid] = 0.f; }

    float o[8][4];
    #pragma unroll
    for (int i = 0; i < 8; i++)
        #pragma unroll
        for (int j2 = 0; j2 < 4; j2++) o[i][j2] = 0.f;

    for (int j = 0; j <= qt; j++) {
        int k0 = j * 64;
        __syncthreads();
        {
            long off = ((long)(b * SQ + k0 + r)) * DQ + h * HDQ + dg * 16;
            int so = r * 144 + dg * 32;
            *(uint4*)(fsm + FOKS + so)      = *(const uint4*)(K16 + off);
            *(uint4*)(fsm + FOKS + so + 16) = *(const uint4*)(K16 + off + 8);
            *(uint4*)(fsm + FOVS + so)      = *(const uint4*)(V16 + off);
            *(uint4*)(fsm + FOVS + so + 16) = *(const uint4*)(V16 + off + 8);
        }
        __syncthreads();

        // S = Q K^T
        float s[4][4];
        #pragma unroll
        for (int na = 0; na < 4; na++)
            #pragma unroll
            for (int v2 = 0; v2 < 4; v2++) s[na][v2] = 0.f;
        #pragma unroll
        for (int kk = 0; kk < 64; kk += 16) {
            uint32_t fah[4], fal[4], fb[4][2];
            uint32_t aro = (uint32_t)((wm * 16 + a_row) * FSTR + kk + a_kof) * 2;
            ldsm4(fah[0], fah[1], fah[2], fah[3], sb + FOQH + aro);
            ldsm4(fal[0], fal[1], fal[2], fal[3], sb + FOQL + aro);
            #pragma unroll
            for (int np = 0; np < 2; np++) {
                uint32_t ro = (uint32_t)((wn * 32 + np * 16 + b_nof) * FSTR + kk + b_kof) * 2;
                ldsm4(fb[2*np][0], fb[2*np][1], fb[2*np+1][0], fb[2*np+1][1], sb + FOKS + ro);
            }
            #pragma unroll
            for (int na = 0; na < 4; na++) mma_f16(s[na], fah, fb[na]);
            #pragma unroll
            for (int na = 0; na < 4; na++) mma_f16(s[na], fal, fb[na]);
        }
        #pragma unroll
        for (int na = 0; na < 4; na++)
            #pragma unroll
            for (int v2 = 0; v2 < 4; v2++) {
                s[na][v2] *= 0.125f;
                if (j == qt) {
                    int kc = wn * 32 + na * 8 + 2 * tig + (v2 & 1);
                    int qr = row0 + (v2 >> 1) * 8;
                    if (kc > qr) s[na][v2] = -1e30f;
                }
            }
        {
            float m0 = -1e30f, m1 = -1e30f;
            #pragma unroll
            for (int na = 0; na < 4; na++) {
                m0 = fmaxf(m0, fmaxf(s[na][0], s[na][1]));
                m1 = fmaxf(m1, fmaxf(s[na][2], s[na][3]));
            }
            m0 = fmaxf(m0, __shfl_xor_sync(0xffffffffu, m0, 1));
            m0 = fmaxf(m0, __shfl_xor_sync(0xffffffffu, m0, 2));
            m1 = fmaxf(m1, __shfl_xor_sync(0xffffffffu, m1, 1));
            m1 = fmaxf(m1, __shfl_xor_sync(0xffffffffu, m1, 2));
            if (tig == 0) { pm[wn * 64 + row0] = m0; pm[wn * 64 + row0 + 8] = m1; }
        }
        __syncthreads();
        if (tid < 64) {
            float mo = rowm[tid];
            float mn = fmaxf(mo, fmaxf(pm[tid], pm[64 + tid]));
            mnew[tid] = mn;
            rowf[tid] = __expf(mo - mn);
            rowm[tid] = mn;
        }
        __syncthreads();

        uint32_t ah[2][4], al[2][4];
        {
            float mn0 = mnew[row0], mn1 = mnew[row0 + 8];
            float sum0 = 0.f, sum1 = 0.f;
            #pragma unroll
            for (int na = 0; na < 4; na++) {
                float p0 = __expf(s[na][0] - mn0);
                float p1 = __expf(s[na][1] - mn0);
                float p2 = __expf(s[na][2] - mn1);
                float p3 = __expf(s[na][3] - mn1);
                sum0 += p0 + p1; sum1 += p2 + p3;
                uint32_t h01, l01, h23, l23;
                splith2(p0, p1, h01, l01);
                splith2(p2, p3, h23, l23);
                int j2 = na >> 1;
                if ((na & 1) == 0) {
                    ah[j2][0] = h01; ah[j2][1] = h23;
                    al[j2][0] = l01; al[j2][1] = l23;
                } else {
                    ah[j2][2] = h01; ah[j2][3] = h23;
                    al[j2][2] = l01; al[j2][3] = l23;
                }
            }
            sum0 += __shfl_xor_sync(0xffffffffu, sum0, 1);
            sum0 += __shfl_xor_sync(0xffffffffu, sum0, 2);
            sum1 += __shfl_xor_sync(0xffffffffu, sum1, 1);
            sum1 += __shfl_xor_sync(0xffffffffu, sum1, 2);
            if (tig == 0) { ps[wn * 64 + row0] = sum0; ps[wn * 64 + row0 + 8] = sum1; }
        }
        __syncthreads();
        if (tid < 64) rowl[tid] = rowl[tid] * rowf[tid] + ps[tid] + ps[64 + tid];

        {
            float f0 = rowf[row0], f1 = rowf[row0 + 8];
            #pragma unroll
            for (int nd = 0; nd < 8; nd++) {
                o[nd][0] *= f0; o[nd][1] *= f0;
                o[nd][2] *= f1; o[nd][3] *= f1;
            }
        }
        #pragma unroll
        for (int jj = 0; jj < 2; jj++) {
            uint32_t fbv[8][2];
            #pragma unroll
            for (int nb = 0; nb < 4; nb++) {
                uint32_t ro = (uint32_t)((wn * 32 + jj * 16 + bt_row) * FSTR + nb * 16 + bt_col) * 2;
                ldsm4t(fbv[2*nb][0], fbv[2*nb][1], fbv[2*nb+1][0], fbv[2*nb+1][1],
                       sb + FOVS + ro);
            }
            #pragma unroll
            for (int nd = 0; nd < 8; nd++) mma_f16(o[nd], ah[jj], fbv[nd]);
            #pragma unroll
            for (int nd = 0; nd < 8; nd++) mma_f16(o[nd], al[jj], fbv[nd]);
        }
    }

    __syncthreads();
    if (wn == 0) {
        #pragma unroll
        for (int nd = 0; nd < 8; nd++)
            #pragma unroll
            for (int v2 = 0; v2 < 4; v2++)
                Osum[(row0 + (v2 >> 1) * 8) * 66 + nd * 8 + 2 * tig + (v2 & 1)] = o[nd][v2];
    }
    __syncthreads();
    if (wn == 1) {
        #pragma unroll
        for (int nd = 0; nd < 8; nd++)
            #pragma unroll
            for (int v2 = 0; v2 < 4; v2++)
                Osum[(row0 + (v2 >> 1) * 8) * 66 + nd * 8 + 2 * tig + (v2 & 1)] += o[nd][v2];
    }
    __syncthreads();
    {
        int orow = tid >> 2, c0 = (tid & 3) * 16;
        float inv = 1.0f / rowl[orow];
        uint32_t hv[8], lv[8];
        #pragma unroll
        for (int i = 0; i < 8; i++) {
            float v0 = Osum[orow * 66 + c0 + 2 * i]     * inv;
            float v1 = Osum[orow * 66 + c0 + 2 * i + 1] * inv;
            splith2(v0, v1, hv[i], lv[i]);
        }
        long base = ((long)(b * SQ + q0 + orow)) * DQ + h * HDQ + c0;
        *(uint4*)&ctxh[base]     = make_uint4(hv[0], hv[1], hv[2], hv[3]);
        *(uint4*)&ctxh[base + 8] = make_uint4(hv[4], hv[5], hv[6], hv[7]);
        *(uint4*)&ctxl[base]     = make_uint4(lv[0], lv[1], lv[2], lv[3]);
        *(uint4*)&ctxl[base + 8] = make_uint4(lv[4], lv[5], lv[6], lv[7]);
    }
}

// ---------------- host orchestration ----------------
extern "C" void kernel_launch(void* const* d_in, const int* in_sizes, int n_in,
                              void* d_out, int out_size) {
    const int*   x    = (const int*)  d_in[0];
    const float* tok  = (const float*)d_in[1];
    const float* pos  = (const float*)d_in[2];
    const float* ln1s = (const float*)d_in[3];
    const float* ln1b = (const float*)d_in[4];
    const float* wq   = (const float*)d_in[5];
    const float* wk   = (const float*)d_in[6];
    const float* wv   = (const float*)d_in[7];
    const float* wo   = (const float*)d_in[8];
    const float* bo   = (const float*)d_in[9];
    const float* ln2s = (const float*)d_in[10];
    const float* ln2b = (const float*)d_in[11];
    const float* w1   = (const float*)d_in[12];
    const float* b1   = (const float*)d_in[13];
    const float* w2   = (const float*)d_in[14];
    const float* b2   = (const float*)d_in[15];
    const float* fs   = (const float*)d_in[16];
    const float* fb   = (const float*)d_in[17];
    const float* wout = (const float*)d_in[18];
    float* out = (float*)d_out;

    float* h;
    uint16_t *qh, *ql, *k16, *v16;
    uint16_t *hnh, *hnl, *ctxh, *ctxl, *ffh, *ffl, *wth;
    cudaGetSymbolAddress((void**)&h,    g_h);
    cudaGetSymbolAddress((void**)&qh,   g_qh);
    cudaGetSymbolAddress((void**)&ql,   g_ql);
    cudaGetSymbolAddress((void**)&k16,  g_k16);
    cudaGetSymbolAddress((void**)&v16,  g_v16);
    cudaGetSymbolAddress((void**)&hnh,  g_hnh);
    cudaGetSymbolAddress((void**)&hnl,  g_hnl);
    cudaGetSymbolAddress((void**)&ctxh, g_ctxh);
    cudaGetSymbolAddress((void**)&ctxl, g_ctxl);
    cudaGetSymbolAddress((void**)&ffh,  g_ffh);
    cudaGetSymbolAddress((void**)&ffl,  g_ffl);
    cudaGetSymbolAddress((void**)&wth,  g_wth);

    const int GSMEM = 3 * STG;   // 110592
    cudaFuncSetAttribute(gpt_flash, cudaFuncAttributeMaxDynamicSharedMemorySize, FLASH_SMEM);
    cudaFuncSetAttribute((const void*)gpt_bmma<2, false, true>,  cudaFuncAttributeMaxDynamicSharedMemorySize, GSMEM);
    cudaFuncSetAttribute((const void*)gpt_bmma<3, false, true>,  cudaFuncAttributeMaxDynamicSharedMemorySize, GSMEM);
    cudaFuncSetAttribute((const void*)gpt_bmma<0, true, false>,  cudaFuncAttributeMaxDynamicSharedMemorySize, GSMEM);
    cudaFuncSetAttribute((const void*)gpt_bmma_qkv,              cudaFuncAttributeMaxDynamicSharedMemorySize, GSMEM);

    dim3 wt(32, 8);
    gpt_wsplit<<<dim3(24, 24, 12), wt>>>(wq,  wth + WQ_OFF,  DQ, DQ, DQ,  (long)DQ*DQ,  (long)LSZ);
    gpt_wsplit<<<dim3(24, 24, 12), wt>>>(wk,  wth + WK_OFF,  DQ, DQ, DQ,  (long)DQ*DQ,  (long)LSZ);
    gpt_wsplit<<<dim3(24, 24, 12), wt>>>(wv,  wth + WV_OFF,  DQ, DQ, DQ,  (long)DQ*DQ,  (long)LSZ);
    gpt_wsplit<<<dim3(24, 24, 12), wt>>>(wo,  wth + WO_OFF,  DQ, DQ, DQ,  (long)DQ*DQ,  (long)LSZ);
    gpt_wsplit<<<dim3(96, 24, 12), wt>>>(w1,  wth + W1T_OFF, DQ, FFQ, FFQ, (long)DQ*FFQ, (long)LSZ);
    gpt_wsplit<<<dim3(24, 96, 12), wt>>>(w2,  wth + W2T_OFF, FFQ, DQ, DQ,  (long)FFQ*DQ, (long)LSZ);
    gpt_wsplit<<<dim3(VQP / 32, 24, 1), wt>>>(wout, wth + WOUT_OFF, DQ, VQ, VQP, 0, 0);

    gpt_embed<<<(NT * DQ + 255) / 256, 256>>>(x, tok, pos, h);

    dim3 gP (DQ / 128,  NT / 64);
    dim3 gQ (DQ / 128,  NT / 64, 3);
    dim3 gF1(FFQ / 128, NT / 64);
    dim3 gV (VQP / 128, 8);
    dim3 gFl(SQ / 64,   BQ * HQ);

    for (int l = 0; l < LQ; l++) {
        long lo = (long)l * LSZ;

        gpt_ln<<<NT, 256>>>(h, ln1s + l * DQ, ln1b + l * DQ, hnh, hnl);

        gpt_bmma_qkv<<<gQ, 256, GSMEM>>>(hnh, hnl, wth + lo + WQ_OFF, qh, ql, k16, v16);

        gpt_flash<<<gFl, 256, FLASH_SMEM>>>(qh, ql, k16, v16, ctxh, ctxl);

        gpt_bmma<2, false, true><<<gP, 256, GSMEM>>>(ctxh, ctxl,
            wth + lo + WO_OFF, bo + l * DQ, h, h, nullptr, nullptr, DQ, DQ, DQ, 1);

        gpt_ln<<<NT, 256>>>(h, ln2s + l * DQ, ln2b + l * DQ, hnh, hnl);

        gpt_bmma<3, false, true><<<gF1, 256, GSMEM>>>(hnh, hnl,
            wth + lo + W1T_OFF, b1 + l * FFQ, nullptr, nullptr, ffh, ffl, FFQ, DQ, FFQ, 1);

        gpt_bmma<2, false, true><<<gP, 256, GSMEM>>>(ffh, ffl,
            wth + lo + W2T_OFF, b2 + l * DQ, h, h, nullptr, nullptr, DQ, FFQ, DQ, 1);
    }

    gpt_ln<<<NT, 256>>>(h, fs, fb, hnh, hnl);

    // vocab: single-chain (activation hi only) — one-shot output, error non-compounding
    gpt_bmma<0, true, false><<<gV, 256, GSMEM>>>(hnh, hnl,
        wth + WOUT_OFF, nullptr, nullptr, out, nullptr, nullptr, VQ, DQ, VQ, 4);
}

// round 16
// speedup vs baseline: 1.8409x; 1.0135x over previous
#include <cuda_runtime.h>
#include <cuda_fp16.h>
#include <math.h>
#include <stdint.h>

// ---------------- problem constants ----------------
#define BQ   4
#define SQ   512
#define DQ   768
#define HQ   12
#define HDQ  64
#define LQ   12
#define VQ   50257
#define VQP  50304
#define FFQ  3072
#define NT   (BQ*SQ)

#define WQ_OFF  0
#define WK_OFF  589824
#define WV_OFF  1179648
#define WO_OFF  1769472
#define W1T_OFF 2359296
#define W2T_OFF 4718592
#define LSZ     7077888
#define WOUT_OFF (12*LSZ)
#define WTOT     (WOUT_OFF + (long)VQP*DQ)

// ---------------- static scratch ----------------
__device__ __align__(128) float    g_h   [NT*DQ];
__device__ __align__(128) uint16_t g_qh  [NT*DQ],  g_ql  [NT*DQ];
__device__ __align__(128) uint16_t g_k16 [NT*DQ],  g_v16 [NT*DQ];
__device__ __align__(128) uint16_t g_hnh [NT*DQ],  g_hnl [NT*DQ];
__device__ __align__(128) uint16_t g_ctxh[NT*DQ],  g_ctxl[NT*DQ];
__device__ __align__(128) uint16_t g_ffh [NT*FFQ], g_ffl [NT*FFQ];
__device__ __align__(128) uint16_t g_wth [WTOT];   // fp16 W^T

// ---------------- helpers ----------------
__device__ __forceinline__ float gelu_f(float x) {
    const float c = 0.7978845608028654f;
    float x3 = x * x * x;
    return 0.5f * x * (1.0f + tanhf(c * (x + 0.044715f * x3)));
}

__device__ __forceinline__ uint32_t smem_u32(const void* p) {
    uint32_t a;
    asm("{ .reg .u64 t; cvta.to.shared.u64 t, %1; cvt.u32.u64 %0, t; }" : "=r"(a) : "l"(p));
    return a;
}

__device__ __forceinline__ void splith2(float a, float b, uint32_t& hi, uint32_t& lo) {
    __half ha = __float2half_rn(a), hb = __float2half_rn(b);
    float ra = a - __half2float(ha), rb = b - __half2float(hb);
    __half la = __float2half_rn(ra), lb = __float2half_rn(rb);
    hi = ((uint32_t)__half_as_ushort(hb) << 16) | (uint32_t)__half_as_ushort(ha);
    lo = ((uint32_t)__half_as_ushort(lb) << 16) | (uint32_t)__half_as_ushort(la);
}

__device__ __forceinline__ uint32_t packh2(float a, float b) {
    __half2 h = __float22half2_rn(make_float2(a, b));
    return *(uint32_t*)&h;
}

__device__ __forceinline__ void ldsm4(uint32_t& r0, uint32_t& r1, uint32_t& r2, uint32_t& r3,
                                      uint32_t addr) {
    asm volatile("ldmatrix.sync.aligned.m8n8.x4.shared.b16 {%0,%1,%2,%3}, [%4];"
        : "=r"(r0), "=r"(r1), "=r"(r2), "=r"(r3) : "r"(addr));
}

__device__ __forceinline__ void ldsm4t(uint32_t& r0, uint32_t& r1, uint32_t& r2, uint32_t& r3,
                                       uint32_t addr) {
    asm volatile("ldmatrix.sync.aligned.m8n8.x4.trans.shared.b16 {%0,%1,%2,%3}, [%4];"
        : "=r"(r0), "=r"(r1), "=r"(r2), "=r"(r3) : "r"(addr));
}

__device__ __forceinline__ void mma_f16(float* c, const uint32_t* a, const uint32_t* b) {
    asm volatile("mma.sync.aligned.m16n8k16.row.col.f32.f16.f16.f32 "
        "{%0,%1,%2,%3}, {%4,%5,%6,%7}, {%8,%9}, {%0,%1,%2,%3};"
        : "+f"(c[0]), "+f"(c[1]), "+f"(c[2]), "+f"(c[3])
        : "r"(a[0]), "r"(a[1]), "r"(a[2]), "r"(a[3]), "r"(b[0]), "r"(b[1]));
}

__device__ __forceinline__ void cpa16(uint32_t saddr, const void* g) {
    asm volatile("cp.async.cg.shared.global [%0], [%1], 16;" :: "r"(saddr), "l"(g));
}

// ---------------- weight transpose + fp16 convert ----------------
__global__ void gpt_wsplit(const float* __restrict__ W, uint16_t* __restrict__ Th,
                           int K, int N, int Npad, long ws, long ts) {
    int l = blockIdx.z;
    W  += (long)l * ws;
    Th += (long)l * ts;
    __shared__ float t[32][33];
    int n0 = blockIdx.x * 32, k0 = blockIdx.y * 32;
    int tx = threadIdx.x, ty = threadIdx.y;
    #pragma unroll
    for (int j = 0; j < 4; j++) {
        int n = n0 + tx;
        t[ty + j * 8][tx] = (n < N) ? W[(long)(k0 + ty + j * 8) * N + n] : 0.f;
    }
    __syncthreads();
    #pragma unroll
    for (int j = 0; j < 4; j++) {
        int n = n0 + ty + j * 8;
        if (n < Npad)
            Th[(long)n * K + k0 + tx] = __half_as_ushort(__float2half_rn(t[tx][ty + j * 8]));
    }
}

// ---------------- embedding ----------------
__global__ void gpt_embed(const int* __restrict__ x, const float* __restrict__ tok,
                          const float* __restrict__ pos, float* __restrict__ h) {
    int i = blockIdx.x * blockDim.x + threadIdx.x;
    if (i < NT * DQ) {
        int t = i / DQ, d = i - t * DQ;
        int s = t & (SQ - 1);
        h[i] = tok[(long)x[t] * DQ + d] + pos[s * DQ + d];
    }
}

// ---------------- layernorm: single pass, one sync ----------------
__global__ void gpt_ln(const float* __restrict__ in, const float* __restrict__ scale,
                       const float* __restrict__ shift,
                       uint16_t* __restrict__ oh, uint16_t* __restrict__ ol) {
    int t = blockIdx.x;
    const float* row = in + (long)t * DQ;
    int tid = threadIdx.x, lane = tid & 31, wid = tid >> 5;
    __shared__ float ws[8], wss[8];

    float x0 = row[tid], x1 = row[tid + 256], x2 = row[tid + 512];
    float s = x0 + x1 + x2;
    float ss = x0 * x0 + x1 * x1 + x2 * x2;
    #pragma unroll
    for (int o = 16; o > 0; o >>= 1) {
        s  += __shfl_xor_sync(0xffffffffu, s,  o);
        ss += __shfl_xor_sync(0xffffffffu, ss, o);
    }
    if (lane == 0) { ws[wid] = s; wss[wid] = ss; }
    __syncthreads();
    float S = 0.f, SS = 0.f;
    #pragma unroll
    for (int i = 0; i < 8; i++) { S += ws[i]; SS += wss[i]; }
    float mean = S * (1.0f / DQ);
    float inv = rsqrtf(SS * (1.0f / DQ) - mean * mean + 1e-5f);

    long base = (long)t * DQ;
    #pragma unroll
    for (int p = 0; p < 3; p++) {
        int d = tid + p * 256;
        float xv = (p == 0) ? x0 : (p == 1) ? x1 : x2;
        float v = scale[d] * (xv - mean) * inv + shift[d];
        __half hb = __float2half_rn(v);
        float r = v - __half2float(hb);
        oh[base + d] = __half_as_ushort(hb);
        ol[base + d] = __half_as_ushort(__float2half_rn(r));
    }
}

// ---------------- fp16 GEMM BM=64 (proven path) ----------------
#define BM   64
#define OAL  9216
#define OB   18432
#define STG  36864

template<bool LO>
__device__ __forceinline__ void load_stage(uint32_t sst,
    const uint16_t* __restrict__ Ah, const uint16_t* __restrict__ Al,
    const uint16_t* __restrict__ B,
    int bm, int bn, int K, int c, int tid) {
    #pragma unroll
    for (int p = 0; p < 4; p++) {
        int idx = tid + p * 256;
        int row = idx >> 3, seg = idx & 7;
        long go = (long)(bn + row) * K + c * 64 + seg * 8;
        cpa16(sst + OB + row * 144 + seg * 16, B + go);
    }
    #pragma unroll
    for (int p = 0; p < 2; p++) {
        int idx = tid + p * 256;
        int row = idx >> 3, seg = idx & 7;
        long go = (long)(bm + row) * K + c * 64 + seg * 8;
        uint32_t so = row * 144 + seg * 16;
        cpa16(sst + so, Ah + go);
        if (LO) cpa16(sst + OAL + so, Al + go);
    }
    asm volatile("cp.async.commit_group;" ::: "memory");
}

template<bool LO>
__device__ __forceinline__ void mma_stage(uint32_t sst, float acc[2][4][4],
        int wm, int wn, int a_row, int a_kof, int b_nof, int b_kof) {
    #pragma unroll
    for (int kk = 0; kk < 64; kk += 16) {
        uint32_t fah[2][4], fb[4][2];
        #pragma unroll
        for (int ma = 0; ma < 2; ma++) {
            uint32_t ro = (uint32_t)((wm * 32 + ma * 16 + a_row) * 144 + (kk + a_kof) * 2);
            ldsm4(fah[ma][0], fah[ma][1], fah[ma][2], fah[ma][3], sst + ro);
        }
        #pragma unroll
        for (int np = 0; np < 2; np++) {
            uint32_t ro = (uint32_t)((wn * 32 + np * 16 + b_nof) * 144 + (kk + b_kof) * 2);
            ldsm4(fb[2*np][0], fb[2*np][1], fb[2*np+1][0], fb[2*np+1][1], sst + OB + ro);
        }
        #pragma unroll
        for (int ma = 0; ma < 2; ma++)
            #pragma unroll
            for (int na = 0; na < 4; na++)
                mma_f16(acc[ma][na], fah[ma], fb[na]);
        if (LO) {
            uint32_t fal[2][4];
            #pragma unroll
            for (int ma = 0; ma < 2; ma++) {
                uint32_t ro = (uint32_t)((wm * 32 + ma * 16 + a_row) * 144 + (kk + a_kof) * 2);
                ldsm4(fal[ma][0], fal[ma][1], fal[ma][2], fal[ma][3], sst + OAL + ro);
            }
            #pragma unroll
            for (int ma = 0; ma < 2; ma++)
                #pragma unroll
                for (int na = 0; na < 4; na++)
                    mma_f16(acc[ma][na], fal[ma], fb[na]);
        }
    }
}

// EPI: 0 fp32 plain; 2 fp32 +bias+res; 3 gelu(x+bias)->fp16 hi/lo;
//      4 fp16 hi/lo; 5 fp16 single. NG: guard gn.
template<int EPI, bool NG, bool LO>
__device__ __forceinline__ void bmma_core(
    const uint16_t* __restrict__ Ah, const uint16_t* __restrict__ Al,
    const uint16_t* __restrict__ B,
    const float* __restrict__ bias, const float* __restrict__ res,
    float* __restrict__ C, uint16_t* __restrict__ Ch, uint16_t* __restrict__ Cl,
    int Ntot, int K, int ldc, int miter) {
    extern __shared__ __align__(16) char smem[];
    uint32_t sb = smem_u32(smem);
    int tid = threadIdx.x;
    int lane = tid & 31, wid = tid >> 5;
    int wm = wid >> 2, wn = wid & 3;
    int bn = blockIdx.x * 128;

    int l8 = lane & 7;
    int a_row = ((lane >> 3) & 1) * 8 + l8;
    int a_kof = (lane >> 4) * 8;
    int b_nof = (lane >> 4) * 8 + l8;
    int b_kof = ((lane >> 3) & 1) * 8;
    int g = lane >> 2, tig = lane & 3;
    const int NCH = K >> 6;

    for (int mi = 0; mi < miter; mi++) {
        int bm = (blockIdx.y * miter + mi) * BM;
        if (mi) __syncthreads();

        float acc[2][4][4];
        #pragma unroll
        for (int i = 0; i < 2; i++)
            #pragma unroll
            for (int j = 0; j < 4; j++)
                #pragma unroll
                for (int r2 = 0; r2 < 4; r2++) acc[i][j][r2] = 0.f;

        load_stage<LO>(sb,       Ah, Al, B, bm, bn, K, 0, tid);
        load_stage<LO>(sb + STG, Ah, Al, B, bm, bn, K, 1, tid);

        for (int c = 0; c < NCH; c++) {
            if (c + 1 < NCH) {
                asm volatile("cp.async.wait_group 1;" ::: "memory");
            } else {
                asm volatile("cp.async.wait_group 0;" ::: "memory");
            }
            __syncthreads();
            if (c + 2 < NCH)
                load_stage<LO>(sb + ((c + 2) % 3) * STG, Ah, Al, B, bm, bn, K, c + 2, tid);
            mma_stage<LO>(sb + (c % 3) * STG, acc, wm, wn, a_row, a_kof, b_nof, b_kof);
        }

        #pragma unroll
        for (int ma = 0; ma < 2; ma++) {
            int r0 = bm + wm * 32 + ma * 16 + g;
            #pragma unroll
            for (int na = 0; na < 4; na++) {
                int gn = bn + wn * 32 + na * 8 + 2 * tig;
                #pragma unroll
                for (int half = 0; half < 2; half++) {
                    int gm = r0 + half * 8;
                    float v0 = acc[ma][na][half * 2 + 0];
                    float v1 = acc[ma][na][half * 2 + 1];
                    long gi = (long)gm * ldc + gn;
                    if (NG) {
                        if (gn < Ntot)     C[gi]     = v0;
                        if (gn + 1 < Ntot) C[gi + 1] = v1;
                    } else if (EPI == 3) {
                        v0 = gelu_f(v0 + bias[gn]);
                        v1 = gelu_f(v1 + bias[gn + 1]);
                        uint32_t hh, ll;
                        splith2(v0, v1, hh, ll);
                        *(uint32_t*)&Ch[gi] = hh;
                        *(uint32_t*)&Cl[gi] = ll;
                    } else if (EPI == 4) {
                        uint32_t hh, ll;
                        splith2(v0, v1, hh, ll);
                        *(uint32_t*)&Ch[gi] = hh;
                        *(uint32_t*)&Cl[gi] = ll;
                    } else if (EPI == 5) {
                        *(uint32_t*)&Ch[gi] = packh2(v0, v1);
                    } else {
                        if (EPI == 2) {
                            v0 += bias[gn]     + res[gi];
                            v1 += bias[gn + 1] + res[gi + 1];
                        }
                        *(float2*)&C[gi] = make_float2(v0, v1);
                    }
                }
            }
        }
    }
}

template<int EPI, bool NG, bool LO>
__global__ void __launch_bounds__(256, 2)
gpt_bmma(const uint16_t* __restrict__ Ah, const uint16_t* __restrict__ Al,
         const uint16_t* __restrict__ B,
         const float* __restrict__ bias, const float* __restrict__ res,
         float* __restrict__ C, uint16_t* __restrict__ Ch, uint16_t* __restrict__ Cl,
         int Ntot, int K, int ldc, int miter) {
    bmma_core<EPI, NG, LO>(Ah, Al, B, bias, res, C, Ch, Cl, Ntot, K, ldc, miter);
}

__global__ void __launch_bounds__(256, 2)
gpt_bmma_qkv(const uint16_t* __restrict__ Ah, const uint16_t* __restrict__ Al,
             const uint16_t* __restrict__ Wt,
             uint16_t* __restrict__ qh, uint16_t* __restrict__ ql,
             uint16_t* __restrict__ k16, uint16_t* __restrict__ v16) {
    int z = blockIdx.z;
    const uint16_t* B = Wt + (long)z * 589824;
    if (z == 0)
        bmma_core<4, false, true>(Ah, Al, B, nullptr, nullptr, nullptr, qh, ql, DQ, DQ, DQ, 1);
    else if (z == 1)
        bmma_core<5, false, false>(Ah, Al, B, nullptr, nullptr, nullptr, k16, nullptr, DQ, DQ, DQ, 1);
    else
        bmma_core<5, false, false>(Ah, Al, B, nullptr, nullptr, nullptr, v16, nullptr, DQ, DQ, DQ, 1);
}

// ---------------- fp16 GEMM BM=128 (FFN1): 4m x 2n warps, warp tile 32x64 ----------------
// stage: Ah 128x144 | Al 128x144 | B 128x144 = 55296 B. 2-stage pipeline.
#define OAL2 18432
#define OB2  36864
#define STG2 55296

__device__ __forceinline__ void load_stage2(uint32_t sst,
    const uint16_t* __restrict__ Ah, const uint16_t* __restrict__ Al,
    const uint16_t* __restrict__ B,
    int bm, int bn, int K, int c, int tid) {
    #pragma unroll
    for (int p = 0; p < 4; p++) {
        int idx = tid + p * 256;
        int row = idx >> 3, seg = idx & 7;
        uint32_t so = row * 144 + seg * 16;
        long gco = c * 64 + seg * 8;
        cpa16(sst + OB2 + so, B + (long)(bn + row) * K + gco);
        long ga = (long)(bm + row) * K + gco;
        cpa16(sst + so,        Ah + ga);
        cpa16(sst + OAL2 + so, Al + ga);
    }
    asm volatile("cp.async.commit_group;" ::: "memory");
}

__device__ __forceinline__ void mma_stage2(uint32_t sst, float acc[2][8][4],
        int wm, int wn, int a_row, int a_kof, int b_nof, int b_kof) {
    #pragma unroll
    for (int kk = 0; kk < 64; kk += 16) {
        uint32_t fah[2][4], fb[8][2];
        #pragma unroll
        for (int ma = 0; ma < 2; ma++) {
            uint32_t ro = (uint32_t)((wm * 32 + ma * 16 + a_row) * 144 + (kk + a_kof) * 2);
            ldsm4(fah[ma][0], fah[ma][1], fah[ma][2], fah[ma][3], sst + ro);
        }
        #pragma unroll
        for (int np = 0; np < 4; np++) {
            uint32_t ro = (uint32_t)((wn * 64 + np * 16 + b_nof) * 144 + (kk + b_kof) * 2);
            ldsm4(fb[2*np][0], fb[2*np][1], fb[2*np+1][0], fb[2*np+1][1], sst + OB2 + ro);
        }
        #pragma unroll
        for (int ma = 0; ma < 2; ma++)
            #pragma unroll
            for (int na = 0; na < 8; na++)
                mma_f16(acc[ma][na], fah[ma], fb[na]);
        {
            uint32_t fal[2][4];
            #pragma unroll
            for (int ma = 0; ma < 2; ma++) {
                uint32_t ro = (uint32_t)((wm * 32 + ma * 16 + a_row) * 144 + (kk + a_kof) * 2);
                ldsm4(fal[ma][0], fal[ma][1], fal[ma][2], fal[ma][3], sst + OAL2 + ro);
            }
            #pragma unroll
            for (int ma = 0; ma < 2; ma++)
                #pragma unroll
                for (int na = 0; na < 8; na++)
                    mma_f16(acc[ma][na], fal[ma], fb[na]);
        }
    }
}

// FFN1: dual-chain, EPI gelu(x+bias) -> fp16 hi/lo
__global__ void __launch_bounds__(256, 2)
gpt_bmma_ffn1(const uint16_t* __restrict__ Ah, const uint16_t* __restrict__ Al,
              const uint16_t* __restrict__ B, const float* __restrict__ bias,
              uint16_t* __restrict__ Ch, uint16_t* __restrict__ Cl) {
    extern __shared__ __align__(16) char smem[];
    uint32_t sb = smem_u32(smem);
    int tid = threadIdx.x;
    int lane = tid & 31, wid = tid >> 5;
    int wm = wid >> 1, wn = wid & 1;
    int bn = blockIdx.x * 128, bm = blockIdx.y * 128;

    int l8 = lane & 7;
    int a_row = ((lane >> 3) & 1) * 8 + l8;
    int a_kof = (lane >> 4) * 8;
    int b_nof = (lane >> 4) * 8 + l8;
    int b_kof = ((lane >> 3) & 1) * 8;
    int g = lane >> 2, tig = lane & 3;
    const int NCH = DQ >> 6;   // 12

    float acc[2][8][4];
    #pragma unroll
    for (int i = 0; i < 2; i++)
        #pragma unroll
        for (int j = 0; j < 8; j++)
            #pragma unroll
            for (int r2 = 0; r2 < 4; r2++) acc[i][j][r2] = 0.f;

    load_stage2(sb,        Ah, Al, B, bm, bn, DQ, 0, tid);
    load_stage2(sb + STG2, Ah, Al, B, bm, bn, DQ, 1, tid);

    for (int c = 0; c < NCH; c++) {
        if (c + 1 < NCH) {
            asm volatile("cp.async.wait_group 1;" ::: "memory");
        } else {
            asm volatile("cp.async.wait_group 0;" ::: "memory");
        }
        __syncthreads();
        mma_stage2(sb + (c & 1) * STG2, acc, wm, wn, a_row, a_kof, b_nof, b_kof);
        if (c + 2 < NCH) {
            __syncthreads();
            load_stage2(sb + (c & 1) * STG2, Ah, Al, B, bm, bn, DQ, c + 2, tid);
        }
    }

    #pragma unroll
    for (int ma = 0; ma < 2; ma++) {
        int r0 = bm + wm * 32 + ma * 16 + g;
        #pragma unroll
        for (int na = 0; na < 8; na++) {
            int gn = bn + wn * 64 + na * 8 + 2 * tig;
            #pragma unroll
            for (int half = 0; half < 2; half++) {
                int gm = r0 + half * 8;
                float v0 = gelu_f(acc[ma][na][half * 2 + 0] + bias[gn]);
                float v1 = gelu_f(acc[ma][na][half * 2 + 1] + bias[gn + 1]);
                long gi = (long)gm * FFQ + gn;
                uint32_t hh, ll;
                splith2(v0, v1, hh, ll);
                *(uint32_t*)&Ch[gi] = hh;
                *(uint32_t*)&Cl[gi] = ll;
            }
        }
    }
}

// ---------------- tensor-core flash attention (fp16 inputs) ----------------
#define FSTR 72
#define FOQH 0
#define FOQL 9216
#define FOKS 18432
#define FOVS 27648
#define FOOS 36864
#define FOST 53760
#define FLASH_SMEM 55808

__global__ void __launch_bounds__(256, 2)
gpt_flash(const uint16_t* __restrict__ Qh, const uint16_t* __restrict__ Ql,
          const uint16_t* __restrict__ K16, const uint16_t* __restrict__ V16,
          uint16_t* __restrict__ ctxh, uint16_t* __restrict__ ctxl) {
    extern __shared__ __align__(16) char fsm[];
    uint32_t sb = smem_u32(fsm);
    float* Osum = (float*)(fsm + FOOS);
    float* rowm = (float*)(fsm + FOST);
    float* rowl = rowm + 64;
    float* rowf = rowm + 128;
    float* mnew = rowm + 192;
    float* pm   = rowm + 256;
    float* ps   = rowm + 384;

    int z = blockIdx.y;
    int b = z / HQ, h = z - b * HQ;
    int qt = blockIdx.x, q0 = qt * 64;
    int tid = threadIdx.x, lane = tid & 31, wid = tid >> 5;
    int wm = wid >> 1, wn = wid & 1;
    int r = tid & 63, dg = tid >> 6;

    int l8 = lane & 7;
    int a_row = ((lane >> 3) & 1) * 8 + l8;
    int a_kof = (lane >> 4) * 8;
    int b_nof = (lane >> 4) * 8 + l8;
    int b_kof = ((lane >> 3) & 1) * 8;
    int bt_row = ((lane >> 3) & 1) * 8 + l8;
    int bt_col = (lane >> 4) * 8;
    int g = lane >> 2, tig = lane & 3;
    int row0 = wm * 16 + g;

    {
        long off = ((long)(b * SQ + q0 + r)) * DQ + h * HDQ + dg * 16;
        int so = r * 144 + dg * 32;
        *(uint4*)(fsm + FOQH + so)      = *(const uint4*)(Qh + off);
        *(uint4*)(fsm + FOQH + so + 16) = *(const uint4*)(Qh + off + 8);
        *(uint4*)(fsm + FOQL + so)      = *(const uint4*)(Ql + off);
        *(uint4*)(fsm + FOQL + so + 16) = *(const uint4*)(Ql + off + 8);
    }
    if (tid < 64) { rowm[tid] = -1e30f; rowl[tid] = 0.f; }

    float o[8][4];
    #pragma unroll
    for (int i = 0; i < 8; i++)
        #pragma unroll
        for (int j2 = 0; j2 < 4; j2++) o[i][j2] = 0.f;

    for (int j = 0; j <= qt; j++) {
        int k0 = j * 64;
        __syncthreads();
        {
            long off = ((long)(b * SQ + k0 + r)) * DQ + h * HDQ + dg * 16;
            int so = r * 144 + dg * 32;
            *(uint4*)(fsm + FOKS + so)      = *(const uint4*)(K16 + off);
            *(uint4*)(fsm + FOKS + so + 16) = *(const uint4*)(K16 + off + 8);
            *(uint4*)(fsm + FOVS + so)      = *(const uint4*)(V16 + off);
            *(uint4*)(fsm + FOVS + so + 16) = *(const uint4*)(V16 + off + 8);
        }
        __syncthreads();

        float s[4][4];
        #pragma unroll
        for (int na = 0; na < 4; na++)
            #pragma unroll
            for (int v2 = 0; v2 < 4; v2++) s[na][v2] = 0.f;
        #pragma unroll
        for (int kk = 0; kk < 64; kk += 16) {
            uint32_t fah[4], fal[4], fb[4][2];
            uint32_t aro = (uint32_t)((wm * 16 + a_row) * FSTR + kk + a_kof) * 2;
            ldsm4(fah[0], fah[1], fah[2], fah[3], sb + FOQH + aro);
            ldsm4(fal[0], fal[1], fal[2], fal[3], sb + FOQL + aro);
            #pragma unroll
            for (int np = 0; np < 2; np++) {
                uint32_t ro = (uint32_t)((wn * 32 + np * 16 + b_nof) * FSTR + kk + b_kof) * 2;
                ldsm4(fb[2*np][0], fb[2*np][1], fb[2*np+1][0], fb[2*np+1][1], sb + FOKS + ro);
            }
            #pragma unroll
            for (int na = 0; na < 4; na++) mma_f16(s[na], fah, fb[na]);
            #pragma unroll
            for (int na = 0; na < 4; na++) mma_f16(s[na], fal, fb[na]);
        }
        #pragma unroll
        for (int na = 0; na < 4; na++)
            #pragma unroll
            for (int v2 = 0; v2 < 4; v2++) {
                s[na][v2] *= 0.125f;
                if (j == qt) {
                    int kc = wn * 32 + na * 8 + 2 * tig + (v2 & 1);
                    int qr = row0 + (v2 >> 1) * 8;
                    if (kc > qr) s[na][v2] = -1e30f;
                }
            }
        {
            float m0 = -1e30f, m1 = -1e30f;
            #pragma unroll
            for (int na = 0; na < 4; na++) {
                m0 = fmaxf(m0, fmaxf(s[na][0], s[na][1]));
                m1 = fmaxf(m1, fmaxf(s[na][2], s[na][3]));
            }
            m0 = fmaxf(m0, __shfl_xor_sync(0xffffffffu, m0, 1));
            m0 = fmaxf(m0, __shfl_xor_sync(0xffffffffu, m0, 2));
            m1 = fmaxf(m1, __shfl_xor_sync(0xffffffffu, m1, 1));
            m1 = fmaxf(m1, __shfl_xor_sync(0xffffffffu, m1, 2));
            if (tig == 0) { pm[wn * 64 + row0] = m0; pm[wn * 64 + row0 + 8] = m1; }
        }
        __syncthreads();
        if (tid < 64) {
            float mo = rowm[tid];
            float mn = fmaxf(mo, fmaxf(pm[tid], pm[64 + tid]));
            mnew[tid] = mn;
            rowf[tid] = __expf(mo - mn);
            rowm[tid] = mn;
        }
        __syncthreads();

        uint32_t ah[2][4], al[2][4];
        {
            float mn0 = mnew[row0], mn1 = mnew[row0 + 8];
            float sum0 = 0.f, sum1 = 0.f;
            #pragma unroll
            for (int na = 0; na < 4; na++) {
                float p0 = __expf(s[na][0] - mn0);
                float p1 = __expf(s[na][1] - mn0);
                float p2 = __expf(s[na][2] - mn1);
                float p3 = __expf(s[na][3] - mn1);
                sum0 += p0 + p1; sum1 += p2 + p3;
                uint32_t h01, l01, h23, l23;
                splith2(p0, p1, h01, l01);
                splith2(p2, p3, h23, l23);
                int j2 = na >> 1;
                if ((na & 1) == 0) {
                    ah[j2][0] = h01; ah[j2][1] = h23;
                    al[j2][0] = l01; al[j2][1] = l23;
                } else {
                    ah[j2][2] = h01; ah[j2][3] = h23;
                    al[j2][2] = l01; al[j2][3] = l23;
                }
            }
            sum0 += __shfl_xor_sync(0xffffffffu, sum0, 1);
            sum0 += __shfl_xor_sync(0xffffffffu, sum0, 2);
            sum1 += __shfl_xor_sync(0xffffffffu, sum1, 1);
            sum1 += __shfl_xor_sync(0xffffffffu, sum1, 2);
            if (tig == 0) { ps[wn * 64 + row0] = sum0; ps[wn * 64 + row0 + 8] = sum1; }
        }
        __syncthreads();
        if (tid < 64) rowl[tid] = rowl[tid] * rowf[tid] + ps[tid] + ps[64 + tid];

        {
            float f0 = rowf[row0], f1 = rowf[row0 + 8];
            #pragma unroll
            for (int nd = 0; nd < 8; nd++) {
                o[nd][0] *= f0; o[nd][1] *= f0;
                o[nd][2] *= f1; o[nd][3] *= f1;
            }
        }
        #pragma unroll
        for (int jj = 0; jj < 2; jj++) {
            uint32_t fbv[8][2];
            #pragma unroll
            for (int nb = 0; nb < 4; nb++) {
                uint32_t ro = (uint32_t)((wn * 32 + jj * 16 + bt_row) * FSTR + nb * 16 + bt_col) * 2;
                ldsm4t(fbv[2*nb][0], fbv[2*nb][1], fbv[2*nb+1][0], fbv[2*nb+1][1],
                       sb + FOVS + ro);
            }
            #pragma unroll
            for (int nd = 0; nd < 8; nd++) mma_f16(o[nd], ah[jj], fbv[nd]);
            #pragma unroll
            for (int nd = 0; nd < 8; nd++) mma_f16(o[nd], al[jj], fbv[nd]);
        }
    }

    __syncthreads();
    if (wn == 0) {
        #pragma unroll
        for (int nd = 0; nd < 8; nd++)
            #pragma unroll
            for (int v2 = 0; v2 < 4; v2++)
                Osum[(row0 + (v2 >> 1) * 8) * 66 + nd * 8 + 2 * tig + (v2 & 1)] = o[nd][v2];
    }
    __syncthreads();
    if (wn == 1) {
        #pragma unroll
        for (int nd = 0; nd < 8; nd++)
            #pragma unroll
            for (int v2 = 0; v2 < 4; v2++)
                Osum[(row0 + (v2 >> 1) * 8) * 66 + nd * 8 + 2 * tig + (v2 & 1)] += o[nd][v2];
    }
    __syncthreads();
    {
        int orow = tid >> 2, c0 = (tid & 3) * 16;
        float inv = 1.0f / rowl[orow];
        uint32_t hv[8], lv[8];
        #pragma unroll
        for (int i = 0; i < 8; i++) {
            float v0 = Osum[orow * 66 + c0 + 2 * i]     * inv;
            float v1 = Osum[orow * 66 + c0 + 2 * i + 1] * inv;
            splith2(v0, v1, hv[i], lv[i]);
        }
        long base = ((long)(b * SQ + q0 + orow)) * DQ + h * HDQ + c0;
        *(uint4*)&ctxh[base]     = make_uint4(hv[0], hv[1], hv[2], hv[3]);
        *(uint4*)&ctxh[base + 8] = make_uint4(hv[4], hv[5], hv[6], hv[7]);
        *(uint4*)&ctxl[base]     = make_uint4(lv[0], lv[1], lv[2], lv[3]);
        *(uint4*)&ctxl[base + 8] = make_uint4(lv[4], lv[5], lv[6], lv[7]);
    }
}

// ---------------- host orchestration ----------------
extern "C" void kernel_launch(void* const* d_in, const int* in_sizes, int n_in,
                              void* d_out, int out_size) {
    const int*   x    = (const int*)  d_in[0];
    const float* tok  = (const float*)d_in[1];
    const float* pos  = (const float*)d_in[2];
    const float* ln1s = (const float*)d_in[3];
    const float* ln1b = (const float*)d_in[4];
    const float* wq   = (const float*)d_in[5];
    const float* wk   = (const float*)d_in[6];
    const float* wv   = (const float*)d_in[7];
    const float* wo   = (const float*)d_in[8];
    const float* bo   = (const float*)d_in[9];
    const float* ln2s = (const float*)d_in[10];
    const float* ln2b = (const float*)d_in[11];
    const float* w1   = (const float*)d_in[12];
    const float* b1   = (const float*)d_in[13];
    const float* w2   = (const float*)d_in[14];
    const float* b2   = (const float*)d_in[15];
    const float* fs   = (const float*)d_in[16];
    const float* fb   = (const float*)d_in[17];
    const float* wout = (const float*)d_in[18];
    float* out = (float*)d_out;

    float* h;
    uint16_t *qh, *ql, *k16, *v16;
    uint16_t *hnh, *hnl, *ctxh, *ctxl, *ffh, *ffl, *wth;
    cudaGetSymbolAddress((void**)&h,    g_h);
    cudaGetSymbolAddress((void**)&qh,   g_qh);
    cudaGetSymbolAddress((void**)&ql,   g_ql);
    cudaGetSymbolAddress((void**)&k16,  g_k16);
    cudaGetSymbolAddress((void**)&v16,  g_v16);
    cudaGetSymbolAddress((void**)&hnh,  g_hnh);
    cudaGetSymbolAddress((void**)&hnl,  g_hnl);
    cudaGetSymbolAddress((void**)&ctxh, g_ctxh);
    cudaGetSymbolAddress((void**)&ctxl, g_ctxl);
    cudaGetSymbolAddress((void**)&ffh,  g_ffh);
    cudaGetSymbolAddress((void**)&ffl,  g_ffl);
    cudaGetSymbolAddress((void**)&wth,  g_wth);

    const int GSMEM  = 3 * STG;    // 110592
    const int GSMEM2 = 2 * STG2;   // 110592
    cudaFuncSetAttribute(gpt_flash, cudaFuncAttributeMaxDynamicSharedMemorySize, FLASH_SMEM);
    cudaFuncSetAttribute((const void*)gpt_bmma<2, false, true>,  cudaFuncAttributeMaxDynamicSharedMemorySize, GSMEM);
    cudaFuncSetAttribute((const void*)gpt_bmma<0, true, false>,  cudaFuncAttributeMaxDynamicSharedMemorySize, GSMEM);
    cudaFuncSetAttribute((const void*)gpt_bmma_qkv,              cudaFuncAttributeMaxDynamicSharedMemorySize, GSMEM);
    cudaFuncSetAttribute((const void*)gpt_bmma_ffn1,             cudaFuncAttributeMaxDynamicSharedMemorySize, GSMEM2);

    dim3 wt(32, 8);
    dim3 gP (DQ / 128,  NT / 64);
    dim3 gQ (DQ / 128,  NT / 64, 3);
    dim3 gF1(FFQ / 128, NT / 128);       // BM=128 FFN1
    dim3 gV (VQP / 128, 8);
    dim3 gFl(SQ / 64,   BQ * HQ);

    // ---- prologue ordered so ncu (-s 5 -c 1) captures gpt_bmma_qkv at launch #5 ----
    gpt_embed<<<(NT * DQ + 255) / 256, 256>>>(x, tok, pos, h);                           // 0
    gpt_ln<<<NT, 256>>>(h, ln1s, ln1b, hnh, hnl);                                         // 1
    gpt_wsplit<<<dim3(24, 24, 12), wt>>>(wq,  wth + WQ_OFF,  DQ, DQ, DQ,  (long)DQ*DQ,  (long)LSZ); // 2
    gpt_wsplit<<<dim3(24, 24, 12), wt>>>(wk,  wth + WK_OFF,  DQ, DQ, DQ,  (long)DQ*DQ,  (long)LSZ); // 3
    gpt_wsplit<<<dim3(24, 24, 12), wt>>>(wv,  wth + WV_OFF,  DQ, DQ, DQ,  (long)DQ*DQ,  (long)LSZ); // 4
    gpt_bmma_qkv<<<gQ, 256, GSMEM>>>(hnh, hnl, wth + WQ_OFF, qh, ql, k16, v16);           // 5 <- profiled
    gpt_wsplit<<<dim3(24, 24, 12), wt>>>(wo,  wth + WO_OFF,  DQ, DQ, DQ,  (long)DQ*DQ,  (long)LSZ);
    gpt_wsplit<<<dim3(96, 24, 12), wt>>>(w1,  wth + W1T_OFF, DQ, FFQ, FFQ, (long)DQ*FFQ, (long)LSZ);
    gpt_wsplit<<<dim3(24, 96, 12), wt>>>(w2,  wth + W2T_OFF, FFQ, DQ, DQ,  (long)FFQ*DQ, (long)LSZ);
    gpt_wsplit<<<dim3(VQP / 32, 24, 1), wt>>>(wout, wth + WOUT_OFF, DQ, VQ, VQP, 0, 0);

    for (int l = 0; l < LQ; l++) {
        long lo = (long)l * LSZ;

        if (l > 0) {
            gpt_ln<<<NT, 256>>>(h, ln1s + l * DQ, ln1b + l * DQ, hnh, hnl);
            gpt_bmma_qkv<<<gQ, 256, GSMEM>>>(hnh, hnl, wth + lo + WQ_OFF, qh, ql, k16, v16);
        }

        gpt_flash<<<gFl, 256, FLASH_SMEM>>>(qh, ql, k16, v16, ctxh, ctxl);

        gpt_bmma<2, false, true><<<gP, 256, GSMEM>>>(ctxh, ctxl,
            wth + lo + WO_OFF, bo + l * DQ, h, h, nullptr, nullptr, DQ, DQ, DQ, 1);

        gpt_ln<<<NT, 256>>>(h, ln2s + l * DQ, ln2b + l * DQ, hnh, hnl);

        gpt_bmma_ffn1<<<gF1, 256, GSMEM2>>>(hnh, hnl,
            wth + lo + W1T_OFF, b1 + l * FFQ, ffh, ffl);

        gpt_bmma<2, false, true><<<gP, 256, GSMEM>>>(ffh, ffl,
            wth + lo + W2T_OFF, b2 + l * DQ, h, h, nullptr, nullptr, DQ, FFQ, DQ, 1);
    }

    gpt_ln<<<NT, 256>>>(h, fs, fb, hnh, hnl);

    gpt_bmma<0, true, false><<<gV, 256, GSMEM>>>(hnh, hnl,
        wth + WOUT_OFF, nullptr, nullptr, out, nullptr, nullptr, VQ, DQ, VQ, 4);
}